// round 1
// baseline (speedup 1.0000x reference)
#include <cuda_runtime.h>
#include <cuda_bf16.h>

// ---------------------------------------------------------------------------
// GGN_IO: fused graph-net step.
//   xi = x[i]
//   h1 = relu([x, xi] @ W_n2e^T + b_n2e)     -> relu(x @ Wa^T + c1)
//   h2 = relu(h1 @ W_e2e^T + b_e2e)
//   s  = sum_n adj[n] * h2[n]
//   h  = W_e2n @ s + b_e2n
//   out = xi + (concat(xi, h) @ W_out^T + b_out)
// ---------------------------------------------------------------------------

#define DIMF 128
#define HIDF 256
#define TM   128      // rows per block
#define PAD  132      // padded row length in smem (floats)
#define MAXBLK 1024

__device__ float g_xi[DIMF];
__device__ float g_c1[HIDF];
__device__ float g_partials[MAXBLK * HIDF];

// ---------------------------------------------------------------------------
// K0: compute xi and fused bias c1[j] = b_n2e[j] + sum_k xi[k]*W_n2e[j,128+k]
// ---------------------------------------------------------------------------
__global__ void setup_kernel(const float* __restrict__ x,
                             const int* __restrict__ ip,
                             const float* __restrict__ Wn2e,
                             const float* __restrict__ bn2e) {
    __shared__ float xi[DIMF];
    int t = threadIdx.x;
    int idx = ip[0];
    if (t < DIMF) {
        float v = x[idx * DIMF + t];
        xi[t] = v;
        g_xi[t] = v;
    }
    __syncthreads();
    // 256 threads: each computes one c1[j]
    float c = bn2e[t];
    const float* wr = Wn2e + t * (2 * DIMF) + DIMF;
    #pragma unroll 8
    for (int k = 0; k < DIMF; ++k) c = fmaf(wr[k], xi[k], c);
    g_c1[t] = c;
}

// ---------------------------------------------------------------------------
// K1: main fused kernel. One block = 128 rows.
//   GEMM1 (K=128): h1t[j][r] = relu(c1[j] + sum_k xs[k][r] * Wn2e[j*256+k])
//   GEMM2 (K=256): h2[r][j]  = relu(be2e[j] + sum_k h1t[k][r] * We2e[j*256+k])
//   partials[blk][j] = sum_r adj[r] * h2[r][j]
// Thread layout: 16x16 (tx = col group, ty = row group), 8x8 register tile.
// Column mapping per pass: jl = 4*tx + jj (jj<4)  and  64 + 4*tx + (jj-4).
// ---------------------------------------------------------------------------
__global__ void __launch_bounds__(256, 1)
main_kernel(const float* __restrict__ x,
            const float* __restrict__ adj,
            const float* __restrict__ Wn2e,
            const float* __restrict__ We2e,
            const float* __restrict__ be2e,
            int N) {
    extern __shared__ float sm[];
    float* xs   = sm;                       // [128][PAD]  x transposed: xs[k][r]
    float* h1t  = sm + DIMF * PAD;          // [256][PAD]  h1 transposed: h1t[j][r]
    float* ws   = h1t + HIDF * PAD;         // [8][PAD]    weight K-chunk
    float* red  = ws + 8 * PAD;             // [16][PAD]   row-reduction buffer
    float* adjs = red + 16 * PAD;           // [128]

    const int t  = threadIdx.x;
    const int tx = t & 15;
    const int ty = t >> 4;
    const int rbase = blockIdx.x * TM;

    // ---- load x tile (transposed into smem) and adj tile ----
    for (int idx = t; idx < TM * DIMF; idx += 256) {
        int r = idx >> 7;           // row within tile
        int c = idx & 127;          // feature
        int row = rbase + r;
        float v = (row < N) ? x[row * DIMF + c] : 0.0f;
        xs[c * PAD + r] = v;
    }
    if (t < TM) {
        int row = rbase + t;
        adjs[t] = (row < N) ? adj[row] : 0.0f;
    }

    // =======================  GEMM 1  =======================
    for (int pass = 0; pass < 2; ++pass) {
        const int jbase = pass * 128;
        float acc[8][8];
        #pragma unroll
        for (int i = 0; i < 8; ++i)
            #pragma unroll
            for (int j = 0; j < 8; ++j) acc[i][j] = 0.0f;

        for (int kc = 0; kc < DIMF; kc += 8) {
            __syncthreads();
            // stage W chunk: ws[kk][jl] = Wn2e[(jbase+jl)*256 + kc + kk]
            {
                const int jl = t >> 1;
                const int kq = (t & 1) << 2;
                const float4 w = *(const float4*)(Wn2e + (jbase + jl) * 256 + kc + kq);
                ws[(kq + 0) * PAD + jl] = w.x;
                ws[(kq + 1) * PAD + jl] = w.y;
                ws[(kq + 2) * PAD + jl] = w.z;
                ws[(kq + 3) * PAD + jl] = w.w;
            }
            __syncthreads();
            #pragma unroll
            for (int kk = 0; kk < 8; ++kk) {
                const float4 a0 = *(const float4*)(xs + (kc + kk) * PAD + (ty << 3));
                const float4 a1 = *(const float4*)(xs + (kc + kk) * PAD + (ty << 3) + 4);
                const float4 b0 = *(const float4*)(ws + kk * PAD + (tx << 2));
                const float4 b1 = *(const float4*)(ws + kk * PAD + 64 + (tx << 2));
                const float a[8] = {a0.x, a0.y, a0.z, a0.w, a1.x, a1.y, a1.z, a1.w};
                const float b[8] = {b0.x, b0.y, b0.z, b0.w, b1.x, b1.y, b1.z, b1.w};
                #pragma unroll
                for (int rr = 0; rr < 8; ++rr)
                    #pragma unroll
                    for (int jj = 0; jj < 8; ++jj)
                        acc[rr][jj] = fmaf(a[rr], b[jj], acc[rr][jj]);
            }
        }
        // epilogue: bias(c1) + relu, store transposed into h1t[j][r]
        #pragma unroll
        for (int jj = 0; jj < 8; ++jj) {
            const int jl = (jj < 4) ? ((tx << 2) + jj) : (64 + (tx << 2) + jj - 4);
            const int j  = jbase + jl;
            const float bias = g_c1[j];
            float4 v0, v1;
            v0.x = fmaxf(acc[0][jj] + bias, 0.0f);
            v0.y = fmaxf(acc[1][jj] + bias, 0.0f);
            v0.z = fmaxf(acc[2][jj] + bias, 0.0f);
            v0.w = fmaxf(acc[3][jj] + bias, 0.0f);
            v1.x = fmaxf(acc[4][jj] + bias, 0.0f);
            v1.y = fmaxf(acc[5][jj] + bias, 0.0f);
            v1.z = fmaxf(acc[6][jj] + bias, 0.0f);
            v1.w = fmaxf(acc[7][jj] + bias, 0.0f);
            *(float4*)(h1t + j * PAD + (ty << 3))     = v0;
            *(float4*)(h1t + j * PAD + (ty << 3) + 4) = v1;
        }
    }

    // =======================  GEMM 2  =======================
    for (int pass = 0; pass < 2; ++pass) {
        const int jbase = pass * 128;
        float acc[8][8];
        #pragma unroll
        for (int i = 0; i < 8; ++i)
            #pragma unroll
            for (int j = 0; j < 8; ++j) acc[i][j] = 0.0f;

        for (int kc = 0; kc < HIDF; kc += 8) {
            __syncthreads();   // also orders h1t writes before first read
            {
                const int jl = t >> 1;
                const int kq = (t & 1) << 2;
                const float4 w = *(const float4*)(We2e + (jbase + jl) * 256 + kc + kq);
                ws[(kq + 0) * PAD + jl] = w.x;
                ws[(kq + 1) * PAD + jl] = w.y;
                ws[(kq + 2) * PAD + jl] = w.z;
                ws[(kq + 3) * PAD + jl] = w.w;
            }
            __syncthreads();
            #pragma unroll
            for (int kk = 0; kk < 8; ++kk) {
                const float4 a0 = *(const float4*)(h1t + (kc + kk) * PAD + (ty << 3));
                const float4 a1 = *(const float4*)(h1t + (kc + kk) * PAD + (ty << 3) + 4);
                const float4 b0 = *(const float4*)(ws + kk * PAD + (tx << 2));
                const float4 b1 = *(const float4*)(ws + kk * PAD + 64 + (tx << 2));
                const float a[8] = {a0.x, a0.y, a0.z, a0.w, a1.x, a1.y, a1.z, a1.w};
                const float b[8] = {b0.x, b0.y, b0.z, b0.w, b1.x, b1.y, b1.z, b1.w};
                #pragma unroll
                for (int rr = 0; rr < 8; ++rr)
                    #pragma unroll
                    for (int jj = 0; jj < 8; ++jj)
                        acc[rr][jj] = fmaf(a[rr], b[jj], acc[rr][jj]);
            }
        }
        // epilogue: bias + relu + adjacency-weighted row reduction
        #pragma unroll
        for (int jj = 0; jj < 8; ++jj) {
            const int jl = (jj < 4) ? ((tx << 2) + jj) : (64 + (tx << 2) + jj - 4);
            const int j  = jbase + jl;
            const float bias = be2e[j];
            float s = 0.0f;
            #pragma unroll
            for (int rr = 0; rr < 8; ++rr) {
                float h2 = fmaxf(acc[rr][jj] + bias, 0.0f);
                s = fmaf(adjs[(ty << 3) + rr], h2, s);
            }
            red[ty * PAD + jl] = s;
        }
        __syncthreads();
        if (t < 128) {
            float s = 0.0f;
            #pragma unroll
            for (int ty2 = 0; ty2 < 16; ++ty2) s += red[ty2 * PAD + t];
            g_partials[blockIdx.x * HIDF + jbase + t] = s;
        }
        __syncthreads();
    }
}

// ---------------------------------------------------------------------------
// K2: deterministic fixed-order reduction of partials + tail MLP.
// ---------------------------------------------------------------------------
__global__ void final_kernel(const float* __restrict__ We2n,
                             const float* __restrict__ be2n,
                             const float* __restrict__ Wout,
                             const float* __restrict__ bout,
                             float* __restrict__ out,
                             int nblk) {
    __shared__ float s[HIDF];
    __shared__ float h[HIDF];
    __shared__ float xi[DIMF];
    int t = threadIdx.x;
    if (t < DIMF) xi[t] = g_xi[t];

    float acc = 0.0f;
    for (int b = 0; b < nblk; ++b) acc += g_partials[b * HIDF + t];
    s[t] = acc;
    __syncthreads();

    float hv = be2n[t];
    const float* wr = We2n + t * HIDF;
    #pragma unroll 8
    for (int k = 0; k < HIDF; ++k) hv = fmaf(wr[k], s[k], hv);
    h[t] = hv;
    __syncthreads();

    if (t < DIMF) {
        float o = bout[t];
        const float* wo = Wout + t * (DIMF + HIDF);
        #pragma unroll 8
        for (int k = 0; k < DIMF; ++k) o = fmaf(wo[k], xi[k], o);
        #pragma unroll 8
        for (int k = 0; k < HIDF; ++k) o = fmaf(wo[DIMF + k], h[k], o);
        out[t] = xi[t] + o;
    }
}

// ---------------------------------------------------------------------------
extern "C" void kernel_launch(void* const* d_in, const int* in_sizes, int n_in,
                              void* d_out, int out_size) {
    const float* x    = (const float*)d_in[0];
    const float* adj  = (const float*)d_in[1];
    const int*   ip   = (const int*)  d_in[2];
    const float* Wn2e = (const float*)d_in[3];
    const float* bn2e = (const float*)d_in[4];
    const float* We2e = (const float*)d_in[5];
    const float* be2e = (const float*)d_in[6];
    const float* We2n = (const float*)d_in[7];
    const float* be2n = (const float*)d_in[8];
    const float* Wout = (const float*)d_in[9];
    const float* bout = (const float*)d_in[10];
    float* out = (float*)d_out;

    const int N = in_sizes[1];                 // adj_col length = node count
    const int nblk = (N + TM - 1) / TM;

    const size_t smem = (size_t)(DIMF * PAD + HIDF * PAD + 8 * PAD + 16 * PAD + 128)
                        * sizeof(float);
    cudaFuncSetAttribute(main_kernel,
                         cudaFuncAttributeMaxDynamicSharedMemorySize, (int)smem);

    setup_kernel<<<1, 256>>>(x, ip, Wn2e, bn2e);
    main_kernel<<<nblk, 256, smem>>>(x, adj, Wn2e, We2e, be2e, N);
    final_kernel<<<1, 256>>>(We2n, be2n, Wout, bout, out, nblk);
}

// round 2
// speedup vs baseline: 1.0000x; 1.0000x over previous
#include <cuda_runtime.h>
#include <cuda_bf16.h>

// ---------------------------------------------------------------------------
// GGN_IO: fused graph-net step.
//   xi = x[i]
//   h1 = relu([x, xi] @ W_n2e^T + b_n2e)     -> relu(x @ Wa^T + c1)
//   h2 = relu(h1 @ W_e2e^T + b_e2e)
//   s  = sum_n adj[n] * h2[n]
//   h  = W_e2n @ s + b_e2n
//   out = xi + (concat(xi, h) @ W_out^T + b_out)
// ---------------------------------------------------------------------------

#define DIMF 128
#define HIDF 256
#define TM   128      // rows per block
#define PAD  132      // padded row length in smem (floats)
#define MAXBLK 1024

__device__ float g_xi[DIMF];
__device__ float g_c1[HIDF];
__device__ float g_partials[MAXBLK * HIDF];

// ---------------------------------------------------------------------------
// K0: compute xi and fused bias c1[j] = b_n2e[j] + sum_k xi[k]*W_n2e[j,128+k]
// ---------------------------------------------------------------------------
__global__ void setup_kernel(const float* __restrict__ x,
                             const int* __restrict__ ip,
                             const float* __restrict__ Wn2e,
                             const float* __restrict__ bn2e) {
    __shared__ float xi[DIMF];
    int t = threadIdx.x;
    int idx = ip[0];
    if (t < DIMF) {
        float v = x[idx * DIMF + t];
        xi[t] = v;
        g_xi[t] = v;
    }
    __syncthreads();
    // 256 threads: each computes one c1[j]
    float c = bn2e[t];
    const float* wr = Wn2e + t * (2 * DIMF) + DIMF;
    #pragma unroll 8
    for (int k = 0; k < DIMF; ++k) c = fmaf(wr[k], xi[k], c);
    g_c1[t] = c;
}

// ---------------------------------------------------------------------------
// K1: main fused kernel. One block = 128 rows.
//   GEMM1 (K=128): h1t[j][r] = relu(c1[j] + sum_k xs[k][r] * Wn2e[j*256+k])
//   GEMM2 (K=256): h2[r][j]  = relu(be2e[j] + sum_k h1t[k][r] * We2e[j*256+k])
//   partials[blk][j] = sum_r adj[r] * h2[r][j]
// Thread layout: 16x16 (tx = col group, ty = row group), 8x8 register tile.
// Column mapping per pass: jl = 4*tx + jj (jj<4)  and  64 + 4*tx + (jj-4).
// ---------------------------------------------------------------------------
__global__ void __launch_bounds__(256, 1)
main_kernel(const float* __restrict__ x,
            const float* __restrict__ adj,
            const float* __restrict__ Wn2e,
            const float* __restrict__ We2e,
            const float* __restrict__ be2e,
            int N) {
    extern __shared__ float sm[];
    float* xs   = sm;                       // [128][PAD]  x transposed: xs[k][r]
    float* h1t  = sm + DIMF * PAD;          // [256][PAD]  h1 transposed: h1t[j][r]
    float* ws   = h1t + HIDF * PAD;         // [8][PAD]    weight K-chunk
    float* red  = ws + 8 * PAD;             // [16][PAD]   row-reduction buffer
    float* adjs = red + 16 * PAD;           // [128]

    const int t  = threadIdx.x;
    const int tx = t & 15;
    const int ty = t >> 4;
    const int rbase = blockIdx.x * TM;

    // ---- load x tile (transposed into smem) and adj tile ----
    for (int idx = t; idx < TM * DIMF; idx += 256) {
        int r = idx >> 7;           // row within tile
        int c = idx & 127;          // feature
        int row = rbase + r;
        float v = (row < N) ? x[row * DIMF + c] : 0.0f;
        xs[c * PAD + r] = v;
    }
    if (t < TM) {
        int row = rbase + t;
        adjs[t] = (row < N) ? adj[row] : 0.0f;
    }

    // =======================  GEMM 1  =======================
    for (int pass = 0; pass < 2; ++pass) {
        const int jbase = pass * 128;
        float acc[8][8];
        #pragma unroll
        for (int i = 0; i < 8; ++i)
            #pragma unroll
            for (int j = 0; j < 8; ++j) acc[i][j] = 0.0f;

        for (int kc = 0; kc < DIMF; kc += 8) {
            __syncthreads();
            // stage W chunk: ws[kk][jl] = Wn2e[(jbase+jl)*256 + kc + kk]
            {
                const int jl = t >> 1;
                const int kq = (t & 1) << 2;
                const float4 w = *(const float4*)(Wn2e + (jbase + jl) * 256 + kc + kq);
                ws[(kq + 0) * PAD + jl] = w.x;
                ws[(kq + 1) * PAD + jl] = w.y;
                ws[(kq + 2) * PAD + jl] = w.z;
                ws[(kq + 3) * PAD + jl] = w.w;
            }
            __syncthreads();
            #pragma unroll
            for (int kk = 0; kk < 8; ++kk) {
                const float4 a0 = *(const float4*)(xs + (kc + kk) * PAD + (ty << 3));
                const float4 a1 = *(const float4*)(xs + (kc + kk) * PAD + (ty << 3) + 4);
                const float4 b0 = *(const float4*)(ws + kk * PAD + (tx << 2));
                const float4 b1 = *(const float4*)(ws + kk * PAD + 64 + (tx << 2));
                const float a[8] = {a0.x, a0.y, a0.z, a0.w, a1.x, a1.y, a1.z, a1.w};
                const float b[8] = {b0.x, b0.y, b0.z, b0.w, b1.x, b1.y, b1.z, b1.w};
                #pragma unroll
                for (int rr = 0; rr < 8; ++rr)
                    #pragma unroll
                    for (int jj = 0; jj < 8; ++jj)
                        acc[rr][jj] = fmaf(a[rr], b[jj], acc[rr][jj]);
            }
        }
        // epilogue: bias(c1) + relu, store transposed into h1t[j][r]
        #pragma unroll
        for (int jj = 0; jj < 8; ++jj) {
            const int jl = (jj < 4) ? ((tx << 2) + jj) : (64 + (tx << 2) + jj - 4);
            const int j  = jbase + jl;
            const float bias = g_c1[j];
            float4 v0, v1;
            v0.x = fmaxf(acc[0][jj] + bias, 0.0f);
            v0.y = fmaxf(acc[1][jj] + bias, 0.0f);
            v0.z = fmaxf(acc[2][jj] + bias, 0.0f);
            v0.w = fmaxf(acc[3][jj] + bias, 0.0f);
            v1.x = fmaxf(acc[4][jj] + bias, 0.0f);
            v1.y = fmaxf(acc[5][jj] + bias, 0.0f);
            v1.z = fmaxf(acc[6][jj] + bias, 0.0f);
            v1.w = fmaxf(acc[7][jj] + bias, 0.0f);
            *(float4*)(h1t + j * PAD + (ty << 3))     = v0;
            *(float4*)(h1t + j * PAD + (ty << 3) + 4) = v1;
        }
    }

    // =======================  GEMM 2  =======================
    for (int pass = 0; pass < 2; ++pass) {
        const int jbase = pass * 128;
        float acc[8][8];
        #pragma unroll
        for (int i = 0; i < 8; ++i)
            #pragma unroll
            for (int j = 0; j < 8; ++j) acc[i][j] = 0.0f;

        for (int kc = 0; kc < HIDF; kc += 8) {
            __syncthreads();   // also orders h1t writes before first read
            {
                const int jl = t >> 1;
                const int kq = (t & 1) << 2;
                const float4 w = *(const float4*)(We2e + (jbase + jl) * 256 + kc + kq);
                ws[(kq + 0) * PAD + jl] = w.x;
                ws[(kq + 1) * PAD + jl] = w.y;
                ws[(kq + 2) * PAD + jl] = w.z;
                ws[(kq + 3) * PAD + jl] = w.w;
            }
            __syncthreads();
            #pragma unroll
            for (int kk = 0; kk < 8; ++kk) {
                const float4 a0 = *(const float4*)(h1t + (kc + kk) * PAD + (ty << 3));
                const float4 a1 = *(const float4*)(h1t + (kc + kk) * PAD + (ty << 3) + 4);
                const float4 b0 = *(const float4*)(ws + kk * PAD + (tx << 2));
                const float4 b1 = *(const float4*)(ws + kk * PAD + 64 + (tx << 2));
                const float a[8] = {a0.x, a0.y, a0.z, a0.w, a1.x, a1.y, a1.z, a1.w};
                const float b[8] = {b0.x, b0.y, b0.z, b0.w, b1.x, b1.y, b1.z, b1.w};
                #pragma unroll
                for (int rr = 0; rr < 8; ++rr)
                    #pragma unroll
                    for (int jj = 0; jj < 8; ++jj)
                        acc[rr][jj] = fmaf(a[rr], b[jj], acc[rr][jj]);
            }
        }
        // epilogue: bias + relu + adjacency-weighted row reduction
        #pragma unroll
        for (int jj = 0; jj < 8; ++jj) {
            const int jl = (jj < 4) ? ((tx << 2) + jj) : (64 + (tx << 2) + jj - 4);
            const int j  = jbase + jl;
            const float bias = be2e[j];
            float s = 0.0f;
            #pragma unroll
            for (int rr = 0; rr < 8; ++rr) {
                float h2 = fmaxf(acc[rr][jj] + bias, 0.0f);
                s = fmaf(adjs[(ty << 3) + rr], h2, s);
            }
            red[ty * PAD + jl] = s;
        }
        __syncthreads();
        if (t < 128) {
            float s = 0.0f;
            #pragma unroll
            for (int ty2 = 0; ty2 < 16; ++ty2) s += red[ty2 * PAD + t];
            g_partials[blockIdx.x * HIDF + jbase + t] = s;
        }
        __syncthreads();
    }
}

// ---------------------------------------------------------------------------
// K2: deterministic fixed-order reduction of partials + tail MLP.
// ---------------------------------------------------------------------------
__global__ void final_kernel(const float* __restrict__ We2n,
                             const float* __restrict__ be2n,
                             const float* __restrict__ Wout,
                             const float* __restrict__ bout,
                             float* __restrict__ out,
                             int nblk) {
    __shared__ float s[HIDF];
    __shared__ float h[HIDF];
    __shared__ float xi[DIMF];
    int t = threadIdx.x;
    if (t < DIMF) xi[t] = g_xi[t];

    float acc = 0.0f;
    for (int b = 0; b < nblk; ++b) acc += g_partials[b * HIDF + t];
    s[t] = acc;
    __syncthreads();

    float hv = be2n[t];
    const float* wr = We2n + t * HIDF;
    #pragma unroll 8
    for (int k = 0; k < HIDF; ++k) hv = fmaf(wr[k], s[k], hv);
    h[t] = hv;
    __syncthreads();

    if (t < DIMF) {
        float o = bout[t];
        const float* wo = Wout + t * (DIMF + HIDF);
        #pragma unroll 8
        for (int k = 0; k < DIMF; ++k) o = fmaf(wo[k], xi[k], o);
        #pragma unroll 8
        for (int k = 0; k < HIDF; ++k) o = fmaf(wo[DIMF + k], h[k], o);
        out[t] = xi[t] + o;
    }
}

// ---------------------------------------------------------------------------
extern "C" void kernel_launch(void* const* d_in, const int* in_sizes, int n_in,
                              void* d_out, int out_size) {
    const float* x    = (const float*)d_in[0];
    const float* adj  = (const float*)d_in[1];
    const int*   ip   = (const int*)  d_in[2];
    const float* Wn2e = (const float*)d_in[3];
    const float* bn2e = (const float*)d_in[4];
    const float* We2e = (const float*)d_in[5];
    const float* be2e = (const float*)d_in[6];
    const float* We2n = (const float*)d_in[7];
    const float* be2n = (const float*)d_in[8];
    const float* Wout = (const float*)d_in[9];
    const float* bout = (const float*)d_in[10];
    float* out = (float*)d_out;

    const int N = in_sizes[1];                 // adj_col length = node count
    const int nblk = (N + TM - 1) / TM;

    const size_t smem = (size_t)(DIMF * PAD + HIDF * PAD + 8 * PAD + 16 * PAD + 128)
                        * sizeof(float);
    cudaFuncSetAttribute(main_kernel,
                         cudaFuncAttributeMaxDynamicSharedMemorySize, (int)smem);

    setup_kernel<<<1, 256>>>(x, ip, Wn2e, bn2e);
    main_kernel<<<nblk, 256, smem>>>(x, adj, Wn2e, We2e, be2e, N);
    final_kernel<<<1, 256>>>(We2n, be2n, Wout, bout, out, nblk);
}

// round 4
// speedup vs baseline: 1.7245x; 1.7244x over previous
#include <cuda_runtime.h>
#include <cuda_bf16.h>

#define DIMF 128
#define HIDF 256
#define TM   128
#define MAXBLK 1024
#define H1S  264            // h1 row stride (bf16 elems), conflict-free
#define BSTR 40             // B chunk row stride (bf16 elems), conflict-free

__device__ float g_xi[DIMF];
__device__ float g_c1[HIDF];
__device__ float g_partials[MAXBLK * HIDF];
__device__ float g_p2[16 * HIDF];
__device__ __align__(16) __nv_bfloat16 gWa_hi[HIDF * DIMF];
__device__ __align__(16) __nv_bfloat16 gWa_lo[HIDF * DIMF];
__device__ __align__(16) __nv_bfloat16 gWe_hi[HIDF * HIDF];
__device__ __align__(16) __nv_bfloat16 gWe_lo[HIDF * HIDF];

__device__ __forceinline__ unsigned smem_u32(const void* p) {
    unsigned a;
    asm("{ .reg .u64 t; cvta.to.shared.u64 t, %1; cvt.u32.u64 %0, t; }" : "=r"(a) : "l"(p));
    return a;
}
__device__ __forceinline__ unsigned packpair(float a, float b) {
    return (unsigned)__bfloat16_as_ushort(__float2bfloat16_rn(a)) |
           ((unsigned)__bfloat16_as_ushort(__float2bfloat16_rn(b)) << 16);
}
// split float2 -> (hi bf16x2, lo bf16x2)
__device__ __forceinline__ void split2(float2 p, unsigned& hi, unsigned& lo) {
    __nv_bfloat16 h0 = __float2bfloat16_rn(p.x), h1 = __float2bfloat16_rn(p.y);
    hi = (unsigned)__bfloat16_as_ushort(h0) | ((unsigned)__bfloat16_as_ushort(h1) << 16);
    lo = packpair(p.x - __bfloat162float(h0), p.y - __bfloat162float(h1));
}
#define MMA(c, a, b0_, b1_)                                                     \
    asm volatile("mma.sync.aligned.m16n8k16.row.col.f32.bf16.bf16.f32 "         \
        "{%0,%1,%2,%3},{%4,%5,%6,%7},{%8,%9},{%0,%1,%2,%3};"                    \
        : "+f"((c)[0]), "+f"((c)[1]), "+f"((c)[2]), "+f"((c)[3])                \
        : "r"((a)[0]), "r"((a)[1]), "r"((a)[2]), "r"((a)[3]), "r"(b0_), "r"(b1_))
#define LDM4(r, addr)                                                           \
    asm volatile("ldmatrix.sync.aligned.m8n8.x4.shared.b16 {%0,%1,%2,%3}, [%4];" \
        : "=r"((r)[0]), "=r"((r)[1]), "=r"((r)[2]), "=r"((r)[3]) : "r"(addr))
#define CP_COMMIT() asm volatile("cp.async.commit_group;" ::: "memory")
#define CP_WAIT(n)  asm volatile("cp.async.wait_group %0;" :: "n"(n) : "memory")

// stage one K-chunk (32 k) of B hi+lo [512 rows x 32 k] into smem buffer
__device__ __forceinline__ void load_chunk(unsigned bs_u32, int buf,
        const __nv_bfloat16* __restrict__ hi, const __nv_bfloat16* __restrict__ lo,
        int K, int c, int tid) {
    #pragma unroll
    for (int j = 0; j < 8; ++j) {
        int idx = j * 256 + tid;            // 2048 pieces of 16B
        int row = idx >> 2;                 // 0..511
        int q   = idx & 3;
        const __nv_bfloat16* src =
            (row < 256 ? hi + row * K : lo + (row - 256) * K) + c * 32 + q * 8;
        unsigned dst = bs_u32 + (unsigned)(((buf * 512 + row) * BSTR) * 2 + q * 16);
        asm volatile("cp.async.cg.shared.global [%0], [%1], 16;"
                     :: "r"(dst), "l"(src));
    }
}

// ---- prep: bf16 hi/lo weight images + xi/c1 --------------------------------
__global__ void prep_kernel(const float* __restrict__ x, const int* __restrict__ ip,
                            const float* __restrict__ Wn2e, const float* __restrict__ bn2e,
                            const float* __restrict__ We2e) {
    int t = threadIdx.x;
    if (blockIdx.x == 192) {
        __shared__ float xi[DIMF];
        int idx = ip[0];
        if (t < DIMF) { float v = x[idx * DIMF + t]; xi[t] = v; g_xi[t] = v; }
        __syncthreads();
        float c = bn2e[t];
        const float* wr = Wn2e + t * (2 * DIMF) + DIMF;
        #pragma unroll 8
        for (int k = 0; k < DIMF; ++k) c = fmaf(wr[k], xi[k], c);
        g_c1[t] = c;
        return;
    }
    int gid = blockIdx.x * 256 + t;                    // 0..49151 pair slots
    unsigned hi, lo;
    if (gid < 16384) {                                 // Wa: 256 x 128
        int n = gid >> 6, kp = (gid & 63) * 2;
        float2 p = make_float2(Wn2e[n * 256 + kp], Wn2e[n * 256 + kp + 1]);
        split2(p, hi, lo);
        *(unsigned*)(gWa_hi + n * DIMF + kp) = hi;
        *(unsigned*)(gWa_lo + n * DIMF + kp) = lo;
    } else {                                           // We: 256 x 256
        int l = gid - 16384;
        int n = l >> 7, kp = (l & 127) * 2;
        float2 p = make_float2(We2e[n * 256 + kp], We2e[n * 256 + kp + 1]);
        split2(p, hi, lo);
        *(unsigned*)(gWe_hi + n * HIDF + kp) = hi;
        *(unsigned*)(gWe_lo + n * HIDF + kp) = lo;
    }
}

// ---- main: HMMA bf16 split-3, 128 rows/CTA ---------------------------------
__global__ void __launch_bounds__(256, 1)
main_kernel(const float* __restrict__ x, const float* __restrict__ adj,
            const float* __restrict__ be2e, int N) {
    extern __shared__ __nv_bfloat16 dsm[];
    __nv_bfloat16* h1 = dsm;                         // [2][128][H1S]
    __nv_bfloat16* Bs = dsm + 2 * 128 * H1S;         // [2][512][BSTR]
    __shared__ float c1s[HIDF], b2s[HIDF], adjs[TM];

    const int tid = threadIdx.x;
    const int w = tid >> 5, lane = tid & 31;
    const int g = lane >> 2, t = lane & 3;
    const int nb = w * 32;
    const int rbase = blockIdx.x * TM;

    if (tid < HIDF) { c1s[tid] = g_c1[tid]; b2s[tid] = be2e[tid]; }
    if (tid < TM) { int r = rbase + tid; adjs[tid] = (r < N) ? adj[r] : 0.0f; }

    const unsigned bs_u32 = smem_u32(Bs);
    const unsigned h1_u32 = smem_u32(h1);

    // =========================== GEMM 1 (K=128) ===========================
    for (int pass = 0; pass < 2; ++pass) {
        float acc[4][4][4];
        #pragma unroll
        for (int a = 0; a < 4; ++a)
            #pragma unroll
            for (int b = 0; b < 4; ++b)
                #pragma unroll
                for (int cgi = 0; cgi < 4; ++cgi) acc[a][b][cgi] = 0.0f;

        __syncthreads();
        load_chunk(bs_u32, 0, gWa_hi, gWa_lo, DIMF, 0, tid);
        CP_COMMIT();
        for (int c = 0; c < 4; ++c) {
            if (c < 3) {
                load_chunk(bs_u32, (c + 1) & 1, gWa_hi, gWa_lo, DIMF, c + 1, tid);
                CP_COMMIT(); CP_WAIT(1);
            } else CP_WAIT(0);
            __syncthreads();
            const __nv_bfloat16* Bb = Bs + (c & 1) * 512 * BSTR;
            #pragma unroll
            for (int kk = 0; kk < 2; ++kk) {
                const int kg = c * 32 + kk * 16;
                unsigned ah[4][4], al[4][4];
                #pragma unroll
                for (int mt = 0; mt < 4; ++mt) {
                    int r0 = rbase + pass * 64 + mt * 16 + g;
                    int r1 = r0 + 8;
                    float2 z = make_float2(0.0f, 0.0f);
                    float2 p0 = (r0 < N) ? *(const float2*)(x + (size_t)r0 * DIMF + kg + 2 * t) : z;
                    float2 p1 = (r1 < N) ? *(const float2*)(x + (size_t)r1 * DIMF + kg + 2 * t) : z;
                    float2 p2 = (r0 < N) ? *(const float2*)(x + (size_t)r0 * DIMF + kg + 8 + 2 * t) : z;
                    float2 p3 = (r1 < N) ? *(const float2*)(x + (size_t)r1 * DIMF + kg + 8 + 2 * t) : z;
                    split2(p0, ah[mt][0], al[mt][0]);
                    split2(p1, ah[mt][1], al[mt][1]);
                    split2(p2, ah[mt][2], al[mt][2]);
                    split2(p3, ah[mt][3], al[mt][3]);
                }
                #pragma unroll
                for (int nt = 0; nt < 4; ++nt) {
                    const __nv_bfloat16* bp = Bb + (nb + nt * 8 + g) * BSTR + kk * 16 + 2 * t;
                    unsigned bh0 = *(const unsigned*)bp;
                    unsigned bh1 = *(const unsigned*)(bp + 8);
                    unsigned bl0 = *(const unsigned*)(bp + 256 * BSTR);
                    unsigned bl1 = *(const unsigned*)(bp + 256 * BSTR + 8);
                    #pragma unroll
                    for (int mt = 0; mt < 4; ++mt) {
                        MMA(acc[mt][nt], ah[mt], bh0, bh1);
                        MMA(acc[mt][nt], ah[mt], bl0, bl1);
                        MMA(acc[mt][nt], al[mt], bh0, bh1);
                    }
                }
            }
            __syncthreads();
        }
        // epilogue 1: relu(acc + c1) -> split -> h1 (hi plane 0, lo plane 1)
        #pragma unroll
        for (int mt = 0; mt < 4; ++mt) {
            int lr0 = pass * 64 + mt * 16 + g;
            #pragma unroll
            for (int nt = 0; nt < 4; ++nt) {
                int col = nb + nt * 8 + 2 * t;
                float b0 = c1s[col], b1 = c1s[col + 1];
                float v0 = fmaxf(acc[mt][nt][0] + b0, 0.0f);
                float v1 = fmaxf(acc[mt][nt][1] + b1, 0.0f);
                float v2 = fmaxf(acc[mt][nt][2] + b0, 0.0f);
                float v3 = fmaxf(acc[mt][nt][3] + b1, 0.0f);
                unsigned hi, lo;
                split2(make_float2(v0, v1), hi, lo);
                *(unsigned*)(h1 + (size_t)lr0 * H1S + col) = hi;
                *(unsigned*)(h1 + (size_t)(128 + lr0) * H1S + col) = lo;
                split2(make_float2(v2, v3), hi, lo);
                *(unsigned*)(h1 + (size_t)(lr0 + 8) * H1S + col) = hi;
                *(unsigned*)(h1 + (size_t)(136 + lr0) * H1S + col) = lo;
            }
        }
    }

    // =========================== GEMM 2 (K=256) ===========================
    float colsum[4][2];
    #pragma unroll
    for (int nt = 0; nt < 4; ++nt) { colsum[nt][0] = 0.0f; colsum[nt][1] = 0.0f; }

    const int rr = lane & 7, q = lane >> 3;
    const unsigned arow_off = (unsigned)(((q & 1) << 3) + rr) * (H1S * 2);
    const unsigned akoff = (unsigned)((q >> 1) << 3) * 2;

    for (int pass = 0; pass < 2; ++pass) {
        float acc[4][4][4];
        #pragma unroll
        for (int a = 0; a < 4; ++a)
            #pragma unroll
            for (int b = 0; b < 4; ++b)
                #pragma unroll
                for (int cgi = 0; cgi < 4; ++cgi) acc[a][b][cgi] = 0.0f;

        __syncthreads();
        load_chunk(bs_u32, 0, gWe_hi, gWe_lo, HIDF, 0, tid);
        CP_COMMIT();
        for (int c = 0; c < 8; ++c) {
            if (c < 7) {
                load_chunk(bs_u32, (c + 1) & 1, gWe_hi, gWe_lo, HIDF, c + 1, tid);
                CP_COMMIT(); CP_WAIT(1);
            } else CP_WAIT(0);
            __syncthreads();
            const __nv_bfloat16* Bb = Bs + (c & 1) * 512 * BSTR;
            #pragma unroll
            for (int kk = 0; kk < 2; ++kk) {
                const int kg = c * 32 + kk * 16;
                unsigned ah[4][4], al[4][4];
                #pragma unroll
                for (int mt = 0; mt < 4; ++mt) {
                    int lr = pass * 64 + mt * 16;
                    unsigned base = h1_u32 + (unsigned)lr * (H1S * 2) + arow_off
                                    + (unsigned)kg * 2 + akoff;
                    LDM4(ah[mt], base);
                    LDM4(al[mt], base + 128 * H1S * 2);
                }
                #pragma unroll
                for (int nt = 0; nt < 4; ++nt) {
                    const __nv_bfloat16* bp = Bb + (nb + nt * 8 + g) * BSTR + kk * 16 + 2 * t;
                    unsigned bh0 = *(const unsigned*)bp;
                    unsigned bh1 = *(const unsigned*)(bp + 8);
                    unsigned bl0 = *(const unsigned*)(bp + 256 * BSTR);
                    unsigned bl1 = *(const unsigned*)(bp + 256 * BSTR + 8);
                    #pragma unroll
                    for (int mt = 0; mt < 4; ++mt) {
                        MMA(acc[mt][nt], ah[mt], bh0, bh1);
                        MMA(acc[mt][nt], ah[mt], bl0, bl1);
                        MMA(acc[mt][nt], al[mt], bh0, bh1);
                    }
                }
            }
            __syncthreads();
        }
        // epilogue 2: relu(acc + b2) * adj, accumulate column sums
        #pragma unroll
        for (int mt = 0; mt < 4; ++mt) {
            int lr0 = pass * 64 + mt * 16 + g;
            float a0 = adjs[lr0], a8 = adjs[lr0 + 8];
            #pragma unroll
            for (int nt = 0; nt < 4; ++nt) {
                int col = nb + nt * 8 + 2 * t;
                float b0 = b2s[col], b1 = b2s[col + 1];
                colsum[nt][0] += fmaxf(acc[mt][nt][0] + b0, 0.0f) * a0
                               + fmaxf(acc[mt][nt][2] + b0, 0.0f) * a8;
                colsum[nt][1] += fmaxf(acc[mt][nt][1] + b1, 0.0f) * a0
                               + fmaxf(acc[mt][nt][3] + b1, 0.0f) * a8;
            }
        }
    }
    // reduce over g (lanes stride 4), lanes 0-3 hold final sums
    #pragma unroll
    for (int nt = 0; nt < 4; ++nt) {
        #pragma unroll
        for (int j = 0; j < 2; ++j) {
            float v = colsum[nt][j];
            v += __shfl_down_sync(0xffffffffu, v, 16);
            v += __shfl_down_sync(0xffffffffu, v, 8);
            v += __shfl_down_sync(0xffffffffu, v, 4);
            if (lane < 4)
                g_partials[blockIdx.x * HIDF + nb + nt * 8 + 2 * lane + j] = v;
        }
    }
}

// ---- reduction tree + tail MLP (deterministic) ------------------------------
__global__ void red_kernel(int nblk) {
    int t = threadIdx.x, b = blockIdx.x;
    int r0 = b * 49, r1 = min(nblk, r0 + 49);
    float s = 0.0f;
    for (int r = r0; r < r1; ++r) s += g_partials[r * HIDF + t];
    g_p2[b * HIDF + t] = s;
}
__global__ void final_kernel(const float* __restrict__ We2n, const float* __restrict__ be2n,
                             const float* __restrict__ Wout, const float* __restrict__ bout,
                             float* __restrict__ out) {
    __shared__ float s[HIDF], h[HIDF], xi[DIMF];
    int t = threadIdx.x;
    if (t < DIMF) xi[t] = g_xi[t];
    float acc = 0.0f;
    #pragma unroll
    for (int b = 0; b < 16; ++b) acc += g_p2[b * HIDF + t];
    s[t] = acc;
    __syncthreads();
    float hv = be2n[t];
    const float* wr = We2n + t * HIDF;
    #pragma unroll 8
    for (int k = 0; k < HIDF; ++k) hv = fmaf(wr[k], s[k], hv);
    h[t] = hv;
    __syncthreads();
    if (t < DIMF) {
        float o = bout[t];
        const float* wo = Wout + t * (DIMF + HIDF);
        #pragma unroll 8
        for (int k = 0; k < DIMF; ++k) o = fmaf(wo[k], xi[k], o);
        #pragma unroll 8
        for (int k = 0; k < HIDF; ++k) o = fmaf(wo[DIMF + k], h[k], o);
        out[t] = xi[t] + o;
    }
}

extern "C" void kernel_launch(void* const* d_in, const int* in_sizes, int n_in,
                              void* d_out, int out_size) {
    const float* x    = (const float*)d_in[0];
    const float* adj  = (const float*)d_in[1];
    const int*   ip   = (const int*)  d_in[2];
    const float* Wn2e = (const float*)d_in[3];
    const float* bn2e = (const float*)d_in[4];
    const float* We2e = (const float*)d_in[5];
    const float* be2e = (const float*)d_in[6];
    const float* We2n = (const float*)d_in[7];
    const float* be2n = (const float*)d_in[8];
    const float* Wout = (const float*)d_in[9];
    const float* bout = (const float*)d_in[10];
    float* out = (float*)d_out;

    const int N = in_sizes[1];
    const int nblk = (N + TM - 1) / TM;
    const int dyn = (2 * 128 * H1S + 2 * 512 * BSTR) * 2;   // 217,088 bytes
    cudaFuncSetAttribute(main_kernel, cudaFuncAttributeMaxDynamicSharedMemorySize, dyn);

    prep_kernel<<<193, 256>>>(x, ip, Wn2e, bn2e, We2e);
    main_kernel<<<nblk, 256, dyn>>>(x, adj, be2e, N);
    red_kernel<<<16, 256>>>(nblk);
    final_kernel<<<1, 256>>>(We2n, be2n, Wout, bout, out);
}

// round 6
// speedup vs baseline: 2.4278x; 1.4078x over previous
#include <cuda_runtime.h>
#include <cuda_bf16.h>

#define DIMF 128
#define HIDF 256
#define TM   128
#define MAXBLK 1024
#define H1S  264            // h1 row stride (bf16), conflict-free
#define BSTR 40             // B chunk row stride (bf16), conflict-free

__device__ float g_xi[DIMF];
__device__ float g_c1[HIDF];
__device__ float g_partials[2 * MAXBLK * HIDF];
__device__ float g_p2[16 * HIDF];
__device__ float g_h[HIDF];
__device__ __align__(16) __nv_bfloat16 gWa_hi[HIDF * DIMF];
__device__ __align__(16) __nv_bfloat16 gWa_lo[HIDF * DIMF];
__device__ __align__(16) __nv_bfloat16 gWe_hi[HIDF * HIDF];
__device__ __align__(16) __nv_bfloat16 gWe_lo[HIDF * HIDF];

__device__ __forceinline__ unsigned smem_u32(const void* p) {
    unsigned a;
    asm("{ .reg .u64 t; cvta.to.shared.u64 t, %1; cvt.u32.u64 %0, t; }" : "=r"(a) : "l"(p));
    return a;
}
__device__ __forceinline__ unsigned packpair(float a, float b) {
    return (unsigned)__bfloat16_as_ushort(__float2bfloat16_rn(a)) |
           ((unsigned)__bfloat16_as_ushort(__float2bfloat16_rn(b)) << 16);
}
__device__ __forceinline__ void split2(float2 p, unsigned& hi, unsigned& lo) {
    __nv_bfloat16 h0 = __float2bfloat16_rn(p.x), h1 = __float2bfloat16_rn(p.y);
    hi = (unsigned)__bfloat16_as_ushort(h0) | ((unsigned)__bfloat16_as_ushort(h1) << 16);
    lo = packpair(p.x - __bfloat162float(h0), p.y - __bfloat162float(h1));
}
#define MMA(c, a, b0_, b1_)                                                     \
    asm volatile("mma.sync.aligned.m16n8k16.row.col.f32.bf16.bf16.f32 "         \
        "{%0,%1,%2,%3},{%4,%5,%6,%7},{%8,%9},{%0,%1,%2,%3};"                    \
        : "+f"((c)[0]), "+f"((c)[1]), "+f"((c)[2]), "+f"((c)[3])                \
        : "r"((a)[0]), "r"((a)[1]), "r"((a)[2]), "r"((a)[3]), "r"(b0_), "r"(b1_))
#define LDM4(r, addr)                                                           \
    asm volatile("ldmatrix.sync.aligned.m8n8.x4.shared.b16 {%0,%1,%2,%3}, [%4];" \
        : "=r"((r)[0]), "=r"((r)[1]), "=r"((r)[2]), "=r"((r)[3]) : "r"(addr))
#define CP_COMMIT() asm volatile("cp.async.commit_group;" ::: "memory")
#define CP_WAIT(n)  asm volatile("cp.async.wait_group %0;" :: "n"(n) : "memory")

// stage one K-chunk (32 k) of B hi+lo [512 rows x 32 k] into smem (512 thr)
__device__ __forceinline__ void load_chunk(unsigned bs_u32, int buf,
        const __nv_bfloat16* __restrict__ hi, const __nv_bfloat16* __restrict__ lo,
        int K, int c, int tid) {
    #pragma unroll
    for (int j = 0; j < 4; ++j) {
        int idx = j * 512 + tid;            // 2048 pieces of 16B
        int row = idx >> 2;
        int q   = idx & 3;
        const __nv_bfloat16* src =
            (row < 256 ? hi + row * K : lo + (row - 256) * K) + c * 32 + q * 8;
        unsigned dst = bs_u32 + (unsigned)(((buf * 512 + row) * BSTR) * 2 + q * 16);
        asm volatile("cp.async.cg.shared.global [%0], [%1], 16;" :: "r"(dst), "l"(src));
    }
}

// ---- prep: bf16 hi/lo weight images + xi/c1 --------------------------------
__global__ void prep_kernel(const float* __restrict__ x, const int* __restrict__ ip,
                            const float* __restrict__ Wn2e, const float* __restrict__ bn2e,
                            const float* __restrict__ We2e) {
    int t = threadIdx.x;
    if (blockIdx.x == 192) {
        __shared__ float xi[DIMF];
        int idx = ip[0];
        if (t < DIMF) { float v = x[idx * DIMF + t]; xi[t] = v; g_xi[t] = v; }
        __syncthreads();
        float c = bn2e[t];
        const float* wr = Wn2e + t * (2 * DIMF) + DIMF;
        #pragma unroll 8
        for (int k = 0; k < DIMF; ++k) c = fmaf(wr[k], xi[k], c);
        g_c1[t] = c;
        return;
    }
    int gid = blockIdx.x * 256 + t;
    unsigned hi, lo;
    if (gid < 16384) {                                 // Wa: 256 x 128
        int n = gid >> 6, kp = (gid & 63) * 2;
        float2 p = make_float2(Wn2e[n * 256 + kp], Wn2e[n * 256 + kp + 1]);
        split2(p, hi, lo);
        *(unsigned*)(gWa_hi + n * DIMF + kp) = hi;
        *(unsigned*)(gWa_lo + n * DIMF + kp) = lo;
    } else {                                           // We: 256 x 256
        int l = gid - 16384;
        int n = l >> 7, kp = (l & 127) * 2;
        float2 p = make_float2(We2e[n * 256 + kp], We2e[n * 256 + kp + 1]);
        split2(p, hi, lo);
        *(unsigned*)(gWe_hi + n * HIDF + kp) = hi;
        *(unsigned*)(gWe_lo + n * HIDF + kp) = lo;
    }
}

// ---- main: HMMA bf16 split-3, 512 threads, 128 rows/CTA ---------------------
__global__ void __launch_bounds__(512, 1)
main_kernel(const float* __restrict__ x, const float* __restrict__ adj,
            const float* __restrict__ be2e, int N) {
    extern __shared__ __nv_bfloat16 dsm[];
    __nv_bfloat16* h1 = dsm;                         // [2][128][H1S]
    __nv_bfloat16* Bs = dsm + 2 * 128 * H1S;         // [2][512][BSTR]
    __shared__ float c1s[HIDF], b2s[HIDF], adjs[TM];

    const int tid = threadIdx.x;
    const int w = tid >> 5, lane = tid & 31;
    const int g = lane >> 2, t = lane & 3;
    const int wn = w >> 1, wm = w & 1;               // N strip, M half
    const int nb = wn * 32;
    const int mbase = wm * 64;
    const int rbase = blockIdx.x * TM;

    if (tid < HIDF) { c1s[tid] = g_c1[tid]; b2s[tid] = be2e[tid]; }
    else if (tid < HIDF + TM) {
        int lt = tid - HIDF;
        int r = rbase + lt;
        adjs[lt] = (r < N) ? adj[r] : 0.0f;
    }

    const unsigned bs_u32 = smem_u32(Bs);
    const unsigned h1_u32 = smem_u32(h1);

    float acc[4][4][4];
    unsigned B[4][4];

    // =========================== GEMM 1 (K=128) ===========================
    #pragma unroll
    for (int a = 0; a < 4; ++a)
        #pragma unroll
        for (int b = 0; b < 4; ++b)
            #pragma unroll
            for (int i = 0; i < 4; ++i) acc[a][b][i] = 0.0f;

    __syncthreads();
    load_chunk(bs_u32, 0, gWa_hi, gWa_lo, DIMF, 0, tid);
    CP_COMMIT();
    for (int c = 0; c < 4; ++c) {
        if (c < 3) {
            load_chunk(bs_u32, (c + 1) & 1, gWa_hi, gWa_lo, DIMF, c + 1, tid);
            CP_COMMIT(); CP_WAIT(1);
        } else CP_WAIT(0);
        __syncthreads();
        const __nv_bfloat16* Bb = Bs + (c & 1) * 512 * BSTR;
        #pragma unroll
        for (int kk = 0; kk < 2; ++kk) {
            const int kg = c * 32 + kk * 16;
            #pragma unroll
            for (int nt = 0; nt < 4; ++nt) {
                const __nv_bfloat16* bp = Bb + (nb + nt * 8 + g) * BSTR + kk * 16 + 2 * t;
                B[nt][0] = *(const unsigned*)bp;
                B[nt][1] = *(const unsigned*)(bp + 8);
                B[nt][2] = *(const unsigned*)(bp + 256 * BSTR);
                B[nt][3] = *(const unsigned*)(bp + 256 * BSTR + 8);
            }
            #pragma unroll
            for (int mt = 0; mt < 4; ++mt) {
                int r0 = rbase + mbase + mt * 16 + g;
                int r1 = r0 + 8;
                float2 z = make_float2(0.0f, 0.0f);
                float2 p0 = (r0 < N) ? *(const float2*)(x + (size_t)r0 * DIMF + kg + 2 * t) : z;
                float2 p1 = (r1 < N) ? *(const float2*)(x + (size_t)r1 * DIMF + kg + 2 * t) : z;
                float2 p2 = (r0 < N) ? *(const float2*)(x + (size_t)r0 * DIMF + kg + 8 + 2 * t) : z;
                float2 p3 = (r1 < N) ? *(const float2*)(x + (size_t)r1 * DIMF + kg + 8 + 2 * t) : z;
                unsigned ah[4], al[4];
                split2(p0, ah[0], al[0]);
                split2(p1, ah[1], al[1]);
                split2(p2, ah[2], al[2]);
                split2(p3, ah[3], al[3]);
                #pragma unroll
                for (int nt = 0; nt < 4; ++nt) {
                    MMA(acc[mt][nt], ah, B[nt][0], B[nt][1]);
                    MMA(acc[mt][nt], ah, B[nt][2], B[nt][3]);
                    MMA(acc[mt][nt], al, B[nt][0], B[nt][1]);
                }
            }
        }
        __syncthreads();
    }
    // epilogue 1: relu(acc + c1) -> split -> h1 (hi rows 0-127, lo rows 128-255)
    #pragma unroll
    for (int mt = 0; mt < 4; ++mt) {
        int lr0 = mbase + mt * 16 + g;
        #pragma unroll
        for (int nt = 0; nt < 4; ++nt) {
            int col = nb + nt * 8 + 2 * t;
            float b0 = c1s[col], b1 = c1s[col + 1];
            float v0 = fmaxf(acc[mt][nt][0] + b0, 0.0f);
            float v1 = fmaxf(acc[mt][nt][1] + b1, 0.0f);
            float v2 = fmaxf(acc[mt][nt][2] + b0, 0.0f);
            float v3 = fmaxf(acc[mt][nt][3] + b1, 0.0f);
            unsigned hi, lo;
            split2(make_float2(v0, v1), hi, lo);
            *(unsigned*)(h1 + (size_t)lr0 * H1S + col) = hi;
            *(unsigned*)(h1 + (size_t)(128 + lr0) * H1S + col) = lo;
            split2(make_float2(v2, v3), hi, lo);
            *(unsigned*)(h1 + (size_t)(lr0 + 8) * H1S + col) = hi;
            *(unsigned*)(h1 + (size_t)(136 + lr0) * H1S + col) = lo;
        }
    }

    // =========================== GEMM 2 (K=256) ===========================
    #pragma unroll
    for (int a = 0; a < 4; ++a)
        #pragma unroll
        for (int b = 0; b < 4; ++b)
            #pragma unroll
            for (int i = 0; i < 4; ++i) acc[a][b][i] = 0.0f;

    const int rr = lane & 7, q = lane >> 3;
    const unsigned arow_off = (unsigned)(((q & 1) << 3) + rr) * (H1S * 2);
    const unsigned akoff = (unsigned)((q >> 1) << 3) * 2;

    load_chunk(bs_u32, 0, gWe_hi, gWe_lo, HIDF, 0, tid);
    CP_COMMIT();
    for (int c = 0; c < 8; ++c) {
        if (c < 7) {
            load_chunk(bs_u32, (c + 1) & 1, gWe_hi, gWe_lo, HIDF, c + 1, tid);
            CP_COMMIT(); CP_WAIT(1);
        } else CP_WAIT(0);
        __syncthreads();   // chunk ready; at c=0 also orders h1 writes
        const __nv_bfloat16* Bb = Bs + (c & 1) * 512 * BSTR;
        #pragma unroll
        for (int kk = 0; kk < 2; ++kk) {
            const int kg = c * 32 + kk * 16;
            #pragma unroll
            for (int nt = 0; nt < 4; ++nt) {
                const __nv_bfloat16* bp = Bb + (nb + nt * 8 + g) * BSTR + kk * 16 + 2 * t;
                B[nt][0] = *(const unsigned*)bp;
                B[nt][1] = *(const unsigned*)(bp + 8);
                B[nt][2] = *(const unsigned*)(bp + 256 * BSTR);
                B[nt][3] = *(const unsigned*)(bp + 256 * BSTR + 8);
            }
            #pragma unroll
            for (int mt = 0; mt < 4; ++mt) {
                unsigned base = h1_u32 + (unsigned)(mbase + mt * 16) * (H1S * 2)
                                + arow_off + (unsigned)kg * 2 + akoff;
                unsigned ah[4], al[4];
                LDM4(ah, base);
                LDM4(al, base + 128 * H1S * 2);
                #pragma unroll
                for (int nt = 0; nt < 4; ++nt) {
                    MMA(acc[mt][nt], ah, B[nt][0], B[nt][1]);
                    MMA(acc[mt][nt], ah, B[nt][2], B[nt][3]);
                    MMA(acc[mt][nt], al, B[nt][0], B[nt][1]);
                }
            }
        }
        __syncthreads();
    }
    // epilogue 2: relu(acc + b2) * adj, column sums over this warp's 64 rows
    float colsum[4][2];
    #pragma unroll
    for (int nt = 0; nt < 4; ++nt) { colsum[nt][0] = 0.0f; colsum[nt][1] = 0.0f; }
    #pragma unroll
    for (int mt = 0; mt < 4; ++mt) {
        int lr0 = mbase + mt * 16 + g;
        float a0 = adjs[lr0], a8 = adjs[lr0 + 8];
        #pragma unroll
        for (int nt = 0; nt < 4; ++nt) {
            int col = nb + nt * 8 + 2 * t;
            float b0 = b2s[col], b1 = b2s[col + 1];
            colsum[nt][0] += fmaxf(acc[mt][nt][0] + b0, 0.0f) * a0
                           + fmaxf(acc[mt][nt][2] + b0, 0.0f) * a8;
            colsum[nt][1] += fmaxf(acc[mt][nt][1] + b1, 0.0f) * a0
                           + fmaxf(acc[mt][nt][3] + b1, 0.0f) * a8;
        }
    }
    #pragma unroll
    for (int nt = 0; nt < 4; ++nt) {
        #pragma unroll
        for (int j = 0; j < 2; ++j) {
            float v = colsum[nt][j];
            v += __shfl_down_sync(0xffffffffu, v, 16);
            v += __shfl_down_sync(0xffffffffu, v, 8);
            v += __shfl_down_sync(0xffffffffu, v, 4);
            if (lane < 4)
                g_partials[(size_t)(blockIdx.x * 2 + wm) * HIDF + nb + nt * 8 + 2 * lane + j] = v;
        }
    }
}

// ---- reduction tree (deterministic) -----------------------------------------
__global__ void red_kernel(int nrows) {
    int t = threadIdx.x, b = blockIdx.x;
    int chunk = (nrows + 15) >> 4;
    int r0 = b * chunk, r1 = min(nrows, r0 + chunk);
    float s = 0.0f;
    for (int r = r0; r < r1; ++r) s += g_partials[(size_t)r * HIDF + t];
    g_p2[b * HIDF + t] = s;
}
// ---- h = We2n @ s + be2n : 32 blocks, warp-per-row, coalesced ---------------
__global__ void h_kernel(const float* __restrict__ We2n, const float* __restrict__ be2n) {
    __shared__ float s[HIDF];
    int t = threadIdx.x, w = t >> 5, lane = t & 31;
    float a = 0.0f;
    #pragma unroll
    for (int b = 0; b < 16; ++b) a += g_p2[b * HIDF + t];
    s[t] = a;
    __syncthreads();
    int row = blockIdx.x * 8 + w;
    const float* wr = We2n + row * HIDF;
    float acc = 0.0f;
    #pragma unroll
    for (int i = 0; i < 8; ++i) acc += wr[lane + 32 * i] * s[lane + 32 * i];
    #pragma unroll
    for (int o = 16; o >= 1; o >>= 1) acc += __shfl_down_sync(0xffffffffu, acc, o);
    if (lane == 0) g_h[row] = acc + be2n[row];
}
// ---- out = xi + (concat(xi,h) @ Wout^T + bout) : warp-per-row ---------------
__global__ void final_kernel(const float* __restrict__ Wout, const float* __restrict__ bout,
                             float* __restrict__ out) {
    __shared__ float v[DIMF + HIDF];
    int t = threadIdx.x, w = t >> 5, lane = t & 31;
    for (int i = t; i < DIMF + HIDF; i += 256)
        v[i] = (i < DIMF) ? g_xi[i] : g_h[i - DIMF];
    __syncthreads();
    #pragma unroll
    for (int it = 0; it < 16; ++it) {
        int row = w * 16 + it;
        const float* wr = Wout + row * (DIMF + HIDF);
        float acc = 0.0f;
        #pragma unroll
        for (int i = 0; i < 12; ++i) acc += wr[lane + 32 * i] * v[lane + 32 * i];
        #pragma unroll
        for (int o = 16; o >= 1; o >>= 1) acc += __shfl_down_sync(0xffffffffu, acc, o);
        if (lane == 0) out[row] = v[row] + acc + bout[row];
    }
}

extern "C" void kernel_launch(void* const* d_in, const int* in_sizes, int n_in,
                              void* d_out, int out_size) {
    const float* x    = (const float*)d_in[0];
    const float* adj  = (const float*)d_in[1];
    const int*   ip   = (const int*)  d_in[2];
    const float* Wn2e = (const float*)d_in[3];
    const float* bn2e = (const float*)d_in[4];
    const float* We2e = (const float*)d_in[5];
    const float* be2e = (const float*)d_in[6];
    const float* We2n = (const float*)d_in[7];
    const float* be2n = (const float*)d_in[8];
    const float* Wout = (const float*)d_in[9];
    const float* bout = (const float*)d_in[10];
    float* out = (float*)d_out;

    const int N = in_sizes[1];
    const int nblk = (N + TM - 1) / TM;
    const int dyn = (2 * 128 * H1S + 2 * 512 * BSTR) * 2;   // 217,088 bytes
    cudaFuncSetAttribute(main_kernel, cudaFuncAttributeMaxDynamicSharedMemorySize, dyn);

    prep_kernel<<<193, 256>>>(x, ip, Wn2e, bn2e, We2e);
    main_kernel<<<nblk, 512, dyn>>>(x, adj, be2e, N);
    red_kernel<<<16, 256>>>(nblk * 2);
    h_kernel<<<32, 256>>>(We2n, be2n);
    final_kernel<<<1, 256>>>(Wout, bout, out);
}

// round 7
// speedup vs baseline: 2.7884x; 1.1485x over previous
#include <cuda_runtime.h>
#include <cuda_bf16.h>

#define DIMF 128
#define HIDF 256
#define TM   128
#define MAXBLK 1024
#define H1S  264            // h1/xs row stride (bf16), conflict-free
#define BSTR 40             // B chunk row stride (bf16), conflict-free

__device__ float g_xi[DIMF];
__device__ float g_c1[HIDF];
__device__ float g_partials[2 * MAXBLK * HIDF];
__device__ unsigned g_ctr;          // zero-init; reset by last block each run
__device__ __align__(16) __nv_bfloat16 gWa_hi[HIDF * DIMF];
__device__ __align__(16) __nv_bfloat16 gWa_lo[HIDF * DIMF];
__device__ __align__(16) __nv_bfloat16 gWe_hi[HIDF * HIDF];
__device__ __align__(16) __nv_bfloat16 gWe_lo[HIDF * HIDF];

__device__ __forceinline__ unsigned smem_u32(const void* p) {
    unsigned a;
    asm("{ .reg .u64 t; cvta.to.shared.u64 t, %1; cvt.u32.u64 %0, t; }" : "=r"(a) : "l"(p));
    return a;
}
__device__ __forceinline__ unsigned packpair(float a, float b) {
    return (unsigned)__bfloat16_as_ushort(__float2bfloat16_rn(a)) |
           ((unsigned)__bfloat16_as_ushort(__float2bfloat16_rn(b)) << 16);
}
__device__ __forceinline__ void split2(float2 p, unsigned& hi, unsigned& lo) {
    __nv_bfloat16 h0 = __float2bfloat16_rn(p.x), h1 = __float2bfloat16_rn(p.y);
    hi = (unsigned)__bfloat16_as_ushort(h0) | ((unsigned)__bfloat16_as_ushort(h1) << 16);
    lo = packpair(p.x - __bfloat162float(h0), p.y - __bfloat162float(h1));
}
#define MMA(c, a, b0_, b1_)                                                     \
    asm volatile("mma.sync.aligned.m16n8k16.row.col.f32.bf16.bf16.f32 "         \
        "{%0,%1,%2,%3},{%4,%5,%6,%7},{%8,%9},{%0,%1,%2,%3};"                    \
        : "+f"((c)[0]), "+f"((c)[1]), "+f"((c)[2]), "+f"((c)[3])                \
        : "r"((a)[0]), "r"((a)[1]), "r"((a)[2]), "r"((a)[3]), "r"(b0_), "r"(b1_))
#define LDM4(r, addr)                                                           \
    asm volatile("ldmatrix.sync.aligned.m8n8.x4.shared.b16 {%0,%1,%2,%3}, [%4];" \
        : "=r"((r)[0]), "=r"((r)[1]), "=r"((r)[2]), "=r"((r)[3]) : "r"(addr))
#define CP_COMMIT() asm volatile("cp.async.commit_group;" ::: "memory")
#define CP_WAIT(n)  asm volatile("cp.async.wait_group %0;" :: "n"(n) : "memory")

// stage one K-chunk (32 k) of B hi+lo [512 rows x 32 k] into smem (512 thr)
__device__ __forceinline__ void load_chunk(unsigned bs_u32, int buf,
        const __nv_bfloat16* __restrict__ hi, const __nv_bfloat16* __restrict__ lo,
        int K, int c, int tid) {
    #pragma unroll
    for (int j = 0; j < 4; ++j) {
        int idx = j * 512 + tid;            // 2048 pieces of 16B
        int row = idx >> 2;
        int q   = idx & 3;
        const __nv_bfloat16* src =
            (row < 256 ? hi + row * K : lo + (row - 256) * K) + c * 32 + q * 8;
        unsigned dst = bs_u32 + (unsigned)(((buf * 512 + row) * BSTR) * 2 + q * 16);
        asm volatile("cp.async.cg.shared.global [%0], [%1], 16;" :: "r"(dst), "l"(src));
    }
}

// ---- prep: bf16 hi/lo weight images + xi/c1 --------------------------------
__global__ void prep_kernel(const float* __restrict__ x, const int* __restrict__ ip,
                            const float* __restrict__ Wn2e, const float* __restrict__ bn2e,
                            const float* __restrict__ We2e) {
    int t = threadIdx.x;
    if (blockIdx.x == 192) {
        __shared__ float xi[DIMF];
        int idx = ip[0];
        if (t < DIMF) { float v = x[idx * DIMF + t]; xi[t] = v; g_xi[t] = v; }
        __syncthreads();
        int w = t >> 5, lane = t & 31;
        for (int it = 0; it < 32; ++it) {
            int j = w * 32 + it;
            const float* wr = Wn2e + j * 256 + DIMF;
            float acc = 0.0f;
            #pragma unroll
            for (int i = 0; i < 4; ++i) acc += wr[lane + 32 * i] * xi[lane + 32 * i];
            #pragma unroll
            for (int o = 16; o >= 1; o >>= 1) acc += __shfl_down_sync(0xffffffffu, acc, o);
            if (lane == 0) g_c1[j] = acc + bn2e[j];
        }
        return;
    }
    int gid = blockIdx.x * 256 + t;
    unsigned hi, lo;
    if (gid < 16384) {                                 // Wa: 256 x 128
        int n = gid >> 6, kp = (gid & 63) * 2;
        float2 p = make_float2(Wn2e[n * 256 + kp], Wn2e[n * 256 + kp + 1]);
        split2(p, hi, lo);
        *(unsigned*)(gWa_hi + n * DIMF + kp) = hi;
        *(unsigned*)(gWa_lo + n * DIMF + kp) = lo;
    } else {                                           // We: 256 x 256
        int l = gid - 16384;
        int n = l >> 7, kp = (l & 127) * 2;
        float2 p = make_float2(We2e[n * 256 + kp], We2e[n * 256 + kp + 1]);
        split2(p, hi, lo);
        *(unsigned*)(gWe_hi + n * HIDF + kp) = hi;
        *(unsigned*)(gWe_lo + n * HIDF + kp) = lo;
    }
}

// ---- main: HMMA bf16 split-3, 512 threads, 128 rows/CTA, fused tail ---------
__global__ void __launch_bounds__(512, 1)
main_kernel(const float* __restrict__ x, const float* __restrict__ adj,
            const float* __restrict__ be2e,
            const float* __restrict__ We2n, const float* __restrict__ be2n,
            const float* __restrict__ Wout, const float* __restrict__ bout,
            float* __restrict__ out, int N) {
    extern __shared__ __nv_bfloat16 dsm[];
    __nv_bfloat16* h1 = dsm;                         // [2][128][H1S]; also xs
    __nv_bfloat16* Bs = dsm + 2 * 128 * H1S;         // [2][512][BSTR]
    __shared__ float c1s[HIDF], b2s[HIDF], adjs[TM];
    __shared__ unsigned s_islast;

    const int tid = threadIdx.x;
    const int w = tid >> 5, lane = tid & 31;
    const int g = lane >> 2, t = lane & 3;
    const int wn = w >> 1, wm = w & 1;               // N strip, M half
    const int nb = wn * 32;
    const int mbase = wm * 64;
    const int rbase = blockIdx.x * TM;

    if (tid < HIDF) { c1s[tid] = g_c1[tid]; b2s[tid] = be2e[tid]; }
    else if (tid < HIDF + TM) {
        int lt = tid - HIDF;
        int r = rbase + lt;
        adjs[lt] = (r < N) ? adj[r] : 0.0f;
    }

    const unsigned bs_u32 = smem_u32(Bs);
    const unsigned h1_u32 = smem_u32(h1);

    // A-fragment ldmatrix addressing (same for xs and h1)
    const int rr = lane & 7, q = lane >> 3;
    const unsigned arow_off = (unsigned)(((q & 1) << 3) + rr) * (H1S * 2);
    const unsigned akoff = (unsigned)((q >> 1) << 3) * 2;
    // B-fragment ldmatrix addressing: tiles (nt,k-lo),(nt,k-hi),(nt+1,k-lo),(nt+1,k-hi)
    const int bsel = lane >> 3, bln = lane & 7;
    const unsigned b_off = (unsigned)((((bsel >> 1) << 3) + bln) * BSTR + ((bsel & 1) << 3)) * 2;

    float acc[4][4][4];
    unsigned Bh0[4], Bh1[4], Bl0[4], Bl1[4];

    // ---- stage x: split -> xs planes (aliased with h1) ----
    {
        int r = tid >> 2;
        int cq = (tid & 3) << 5;
        int row = rbase + r;
        float f[32];
        if (row < N) {
            const float4* xr = (const float4*)(x + (size_t)row * DIMF + cq);
            #pragma unroll
            for (int qq = 0; qq < 8; ++qq) {
                float4 v = xr[qq];
                f[4*qq] = v.x; f[4*qq+1] = v.y; f[4*qq+2] = v.z; f[4*qq+3] = v.w;
            }
        } else {
            #pragma unroll
            for (int qq = 0; qq < 32; ++qq) f[qq] = 0.0f;
        }
        #pragma unroll
        for (int p = 0; p < 8; ++p) {
            unsigned ha, la, hb, lb;
            split2(make_float2(f[4*p],   f[4*p+1]), ha, la);
            split2(make_float2(f[4*p+2], f[4*p+3]), hb, lb);
            int col = cq + 4 * p;
            *(uint2*)(h1 + (size_t)r * H1S + col)         = make_uint2(ha, hb);
            *(uint2*)(h1 + (size_t)(128 + r) * H1S + col) = make_uint2(la, lb);
        }
    }

    // =========================== GEMM 1 (K=128, xs) ===========================
    #pragma unroll
    for (int a = 0; a < 4; ++a)
        #pragma unroll
        for (int b = 0; b < 4; ++b)
            #pragma unroll
            for (int i = 0; i < 4; ++i) acc[a][b][i] = 0.0f;

    load_chunk(bs_u32, 0, gWa_hi, gWa_lo, DIMF, 0, tid);
    CP_COMMIT();
    for (int c = 0; c < 4; ++c) {
        if (c < 3) {
            load_chunk(bs_u32, (c + 1) & 1, gWa_hi, gWa_lo, DIMF, c + 1, tid);
            CP_COMMIT(); CP_WAIT(1);
        } else CP_WAIT(0);
        __syncthreads();   // chunk ready; c=0 also orders xs staging stores
        const unsigned bufb = bs_u32 + (unsigned)((c & 1) * 512 * BSTR * 2);
        #pragma unroll
        for (int kk = 0; kk < 2; ++kk) {
            const int kg = c * 32 + kk * 16;
            const unsigned bb = bufb + (unsigned)((nb * BSTR + kk * 16) * 2) + b_off;
            { unsigned r4[4]; LDM4(r4, bb);
              Bh0[0]=r4[0]; Bh1[0]=r4[1]; Bh0[1]=r4[2]; Bh1[1]=r4[3]; }
            { unsigned r4[4]; LDM4(r4, bb + 16 * BSTR * 2);
              Bh0[2]=r4[0]; Bh1[2]=r4[1]; Bh0[3]=r4[2]; Bh1[3]=r4[3]; }
            { unsigned r4[4]; LDM4(r4, bb + 256 * BSTR * 2);
              Bl0[0]=r4[0]; Bl1[0]=r4[1]; Bl0[1]=r4[2]; Bl1[1]=r4[3]; }
            { unsigned r4[4]; LDM4(r4, bb + (256 + 16) * BSTR * 2);
              Bl0[2]=r4[0]; Bl1[2]=r4[1]; Bl0[3]=r4[2]; Bl1[3]=r4[3]; }
            #pragma unroll
            for (int mt = 0; mt < 4; ++mt) {
                unsigned base = h1_u32 + (unsigned)(mbase + mt * 16) * (H1S * 2)
                                + arow_off + (unsigned)kg * 2 + akoff;
                unsigned ah[4], al[4];
                LDM4(ah, base);
                LDM4(al, base + 128 * H1S * 2);
                #pragma unroll
                for (int nt = 0; nt < 4; ++nt) {
                    MMA(acc[mt][nt], ah, Bh0[nt], Bh1[nt]);
                    MMA(acc[mt][nt], ah, Bl0[nt], Bl1[nt]);
                    MMA(acc[mt][nt], al, Bh0[nt], Bh1[nt]);
                }
            }
        }
        __syncthreads();
    }
    // prefetch first We chunk while epilogue runs
    load_chunk(bs_u32, 0, gWe_hi, gWe_lo, HIDF, 0, tid);
    CP_COMMIT();
    // epilogue 1: relu(acc + c1) -> split -> h1 (hi rows 0-127, lo rows 128-255)
    #pragma unroll
    for (int mt = 0; mt < 4; ++mt) {
        int lr0 = mbase + mt * 16 + g;
        #pragma unroll
        for (int nt = 0; nt < 4; ++nt) {
            int col = nb + nt * 8 + 2 * t;
            float b0 = c1s[col], b1 = c1s[col + 1];
            float v0 = fmaxf(acc[mt][nt][0] + b0, 0.0f);
            float v1 = fmaxf(acc[mt][nt][1] + b1, 0.0f);
            float v2 = fmaxf(acc[mt][nt][2] + b0, 0.0f);
            float v3 = fmaxf(acc[mt][nt][3] + b1, 0.0f);
            unsigned hi, lo;
            split2(make_float2(v0, v1), hi, lo);
            *(unsigned*)(h1 + (size_t)lr0 * H1S + col) = hi;
            *(unsigned*)(h1 + (size_t)(128 + lr0) * H1S + col) = lo;
            split2(make_float2(v2, v3), hi, lo);
            *(unsigned*)(h1 + (size_t)(lr0 + 8) * H1S + col) = hi;
            *(unsigned*)(h1 + (size_t)(136 + lr0) * H1S + col) = lo;
        }
    }

    // =========================== GEMM 2 (K=256, h1) ===========================
    #pragma unroll
    for (int a = 0; a < 4; ++a)
        #pragma unroll
        for (int b = 0; b < 4; ++b)
            #pragma unroll
            for (int i = 0; i < 4; ++i) acc[a][b][i] = 0.0f;

    for (int c = 0; c < 8; ++c) {
        if (c < 7) {
            load_chunk(bs_u32, (c + 1) & 1, gWe_hi, gWe_lo, HIDF, c + 1, tid);
            CP_COMMIT(); CP_WAIT(1);
        } else CP_WAIT(0);
        __syncthreads();   // chunk ready; c=0 also orders h1 epilogue stores
        const unsigned bufb = bs_u32 + (unsigned)((c & 1) * 512 * BSTR * 2);
        #pragma unroll
        for (int kk = 0; kk < 2; ++kk) {
            const int kg = c * 32 + kk * 16;
            const unsigned bb = bufb + (unsigned)((nb * BSTR + kk * 16) * 2) + b_off;
            { unsigned r4[4]; LDM4(r4, bb);
              Bh0[0]=r4[0]; Bh1[0]=r4[1]; Bh0[1]=r4[2]; Bh1[1]=r4[3]; }
            { unsigned r4[4]; LDM4(r4, bb + 16 * BSTR * 2);
              Bh0[2]=r4[0]; Bh1[2]=r4[1]; Bh0[3]=r4[2]; Bh1[3]=r4[3]; }
            { unsigned r4[4]; LDM4(r4, bb + 256 * BSTR * 2);
              Bl0[0]=r4[0]; Bl1[0]=r4[1]; Bl0[1]=r4[2]; Bl1[1]=r4[3]; }
            { unsigned r4[4]; LDM4(r4, bb + (256 + 16) * BSTR * 2);
              Bl0[2]=r4[0]; Bl1[2]=r4[1]; Bl0[3]=r4[2]; Bl1[3]=r4[3]; }
            #pragma unroll
            for (int mt = 0; mt < 4; ++mt) {
                unsigned base = h1_u32 + (unsigned)(mbase + mt * 16) * (H1S * 2)
                                + arow_off + (unsigned)kg * 2 + akoff;
                unsigned ah[4], al[4];
                LDM4(ah, base);
                LDM4(al, base + 128 * H1S * 2);
                #pragma unroll
                for (int nt = 0; nt < 4; ++nt) {
                    MMA(acc[mt][nt], ah, Bh0[nt], Bh1[nt]);
                    MMA(acc[mt][nt], ah, Bl0[nt], Bl1[nt]);
                    MMA(acc[mt][nt], al, Bh0[nt], Bh1[nt]);
                }
            }
        }
        __syncthreads();
    }
    // epilogue 2: relu(acc + b2) * adj, column sums over this warp's 64 rows
    float colsum[4][2];
    #pragma unroll
    for (int nt = 0; nt < 4; ++nt) { colsum[nt][0] = 0.0f; colsum[nt][1] = 0.0f; }
    #pragma unroll
    for (int mt = 0; mt < 4; ++mt) {
        int lr0 = mbase + mt * 16 + g;
        float a0 = adjs[lr0], a8 = adjs[lr0 + 8];
        #pragma unroll
        for (int nt = 0; nt < 4; ++nt) {
            int col = nb + nt * 8 + 2 * t;
            float b0 = b2s[col], b1 = b2s[col + 1];
            colsum[nt][0] += fmaxf(acc[mt][nt][0] + b0, 0.0f) * a0
                           + fmaxf(acc[mt][nt][2] + b0, 0.0f) * a8;
            colsum[nt][1] += fmaxf(acc[mt][nt][1] + b1, 0.0f) * a0
                           + fmaxf(acc[mt][nt][3] + b1, 0.0f) * a8;
        }
    }
    #pragma unroll
    for (int nt = 0; nt < 4; ++nt) {
        #pragma unroll
        for (int j = 0; j < 2; ++j) {
            float v = colsum[nt][j];
            v += __shfl_down_sync(0xffffffffu, v, 16);
            v += __shfl_down_sync(0xffffffffu, v, 8);
            v += __shfl_down_sync(0xffffffffu, v, 4);
            if (lane < 4)
                g_partials[(size_t)(blockIdx.x * 2 + wm) * HIDF + nb + nt * 8 + 2 * lane + j] = v;
        }
    }

    // ---- fused tail: last CTA reduces partials + runs the small MLPs -------
    __syncthreads();
    if (tid == 0) {
        __threadfence();
        unsigned old = atomicAdd(&g_ctr, 1u);
        s_islast = (old == gridDim.x - 1) ? 1u : 0u;
    }
    __syncthreads();
    if (!s_islast) return;
    __threadfence();

    __shared__ float ss[HIDF];
    __shared__ float sv[DIMF + HIDF];
    const int R = gridDim.x * 2;
    {
        int col = tid & 255, half = tid >> 8;
        float a = 0.0f;
        for (int r = half; r < R; r += 2) a += g_partials[(size_t)r * HIDF + col];
        if (half == 0) ss[col] = a;
        __syncthreads();
        if (half == 1) ss[col] += a;
    }
    if (tid < DIMF) sv[tid] = g_xi[tid];
    __syncthreads();
    // h = We2n @ s + be2n : 16 warps x 16 rows, coalesced
    for (int it = 0; it < 16; ++it) {
        int row = w * 16 + it;
        const float* wr = We2n + row * HIDF;
        float a = 0.0f;
        #pragma unroll
        for (int i = 0; i < 8; ++i) a += wr[lane + 32 * i] * ss[lane + 32 * i];
        #pragma unroll
        for (int o = 16; o >= 1; o >>= 1) a += __shfl_down_sync(0xffffffffu, a, o);
        if (lane == 0) sv[DIMF + row] = a + be2n[row];
    }
    __syncthreads();
    // out = xi + concat(xi,h) @ Wout^T + bout : 16 warps x 8 rows
    for (int it = 0; it < 8; ++it) {
        int row = w * 8 + it;
        const float* wr = Wout + row * (DIMF + HIDF);
        float a = 0.0f;
        #pragma unroll
        for (int i = 0; i < 12; ++i) a += wr[lane + 32 * i] * sv[lane + 32 * i];
        #pragma unroll
        for (int o = 16; o >= 1; o >>= 1) a += __shfl_down_sync(0xffffffffu, a, o);
        if (lane == 0) out[row] = sv[row] + a + bout[row];
    }
    if (tid == 0) g_ctr = 0;   // reset for next graph replay
}

extern "C" void kernel_launch(void* const* d_in, const int* in_sizes, int n_in,
                              void* d_out, int out_size) {
    const float* x    = (const float*)d_in[0];
    const float* adj  = (const float*)d_in[1];
    const int*   ip   = (const int*)  d_in[2];
    const float* Wn2e = (const float*)d_in[3];
    const float* bn2e = (const float*)d_in[4];
    const float* We2e = (const float*)d_in[5];
    const float* be2e = (const float*)d_in[6];
    const float* We2n = (const float*)d_in[7];
    const float* be2n = (const float*)d_in[8];
    const float* Wout = (const float*)d_in[9];
    const float* bout = (const float*)d_in[10];
    float* out = (float*)d_out;

    const int N = in_sizes[1];
    const int nblk = (N + TM - 1) / TM;
    const int dyn = (2 * 128 * H1S + 2 * 512 * BSTR) * 2;   // 217,088 bytes
    cudaFuncSetAttribute(main_kernel, cudaFuncAttributeMaxDynamicSharedMemorySize, dyn);

    prep_kernel<<<193, 256>>>(x, ip, Wn2e, bn2e, We2e);
    main_kernel<<<nblk, 512, dyn>>>(x, adj, be2e, We2n, be2n, Wout, bout, out, N);
}

// round 8
// speedup vs baseline: 3.2252x; 1.1567x over previous
#include <cuda_runtime.h>
#include <cuda_bf16.h>

#define DIMF 128
#define HIDF 256
#define TM   128
#define MAXBLK 1024
#define H1S  264            // h1/xs row stride (bf16), conflict-free
#define BSTR 40             // B chunk row stride (bf16), conflict-free
#define CHUNKB 40960        // 512 rows * 40 bf16 * 2B

__device__ float g_xi[DIMF];
__device__ float g_c1[HIDF];
__device__ float g_partials[2 * MAXBLK * HIDF];
__device__ unsigned g_ctr;
// chunk-blocked, padded weight images: [chunk][512 rows][40 bf16]
__device__ __align__(16) __nv_bfloat16 gWaP[4 * 512 * BSTR];
__device__ __align__(16) __nv_bfloat16 gWeP[8 * 512 * BSTR];

__device__ __forceinline__ unsigned smem_u32(const void* p) {
    unsigned a;
    asm("{ .reg .u64 t; cvta.to.shared.u64 t, %1; cvt.u32.u64 %0, t; }" : "=r"(a) : "l"(p));
    return a;
}
__device__ __forceinline__ unsigned packpair(float a, float b) {
    return (unsigned)__bfloat16_as_ushort(__float2bfloat16_rn(a)) |
           ((unsigned)__bfloat16_as_ushort(__float2bfloat16_rn(b)) << 16);
}
__device__ __forceinline__ void split2(float2 p, unsigned& hi, unsigned& lo) {
    __nv_bfloat16 h0 = __float2bfloat16_rn(p.x), h1 = __float2bfloat16_rn(p.y);
    hi = (unsigned)__bfloat16_as_ushort(h0) | ((unsigned)__bfloat16_as_ushort(h1) << 16);
    lo = packpair(p.x - __bfloat162float(h0), p.y - __bfloat162float(h1));
}
#define MMA(c, a, b0_, b1_)                                                     \
    asm volatile("mma.sync.aligned.m16n8k16.row.col.f32.bf16.bf16.f32 "         \
        "{%0,%1,%2,%3},{%4,%5,%6,%7},{%8,%9},{%0,%1,%2,%3};"                    \
        : "+f"((c)[0]), "+f"((c)[1]), "+f"((c)[2]), "+f"((c)[3])                \
        : "r"((a)[0]), "r"((a)[1]), "r"((a)[2]), "r"((a)[3]), "r"(b0_), "r"(b1_))
#define LDM4(r, addr)                                                           \
    asm volatile("ldmatrix.sync.aligned.m8n8.x4.shared.b16 {%0,%1,%2,%3}, [%4];" \
        : "=r"((r)[0]), "=r"((r)[1]), "=r"((r)[2]), "=r"((r)[3]) : "r"(addr))
#define MBI(a, c) asm volatile("mbarrier.init.shared.b64 [%0], %1;" :: "r"(a), "r"(c) : "memory")
#define MBTX(a, b) asm volatile("mbarrier.arrive.expect_tx.shared.b64 _, [%0], %1;" :: "r"(a), "r"(b) : "memory")
#define MBWAIT(a, ph) do {                                                    \
    unsigned _m = (a), _p = (ph), _d;                                         \
    asm volatile("{ .reg .pred p; mbarrier.try_wait.parity.acquire.cta.shared::cta.b64 p, [%1], %2;" \
                 " selp.b32 %0, 1, 0, p; }" : "=r"(_d) : "r"(_m), "r"(_p) : "memory"); \
    if (!_d) asm volatile("{ .reg .pred P1; WL%=:"                            \
        " mbarrier.try_wait.parity.acquire.cta.shared::cta.b64 P1, [%0], %1, 0x989680;" \
        " @P1 bra.uni WD%=; bra.uni WL%=; WD%=: }" :: "r"(_m), "r"(_p) : "memory"); \
    } while (0)
__device__ __forceinline__ void bulk_g2s(unsigned dst, const void* src,
                                         unsigned bytes, unsigned mbar) {
    asm volatile("cp.async.bulk.shared::cluster.global.mbarrier::complete_tx::bytes [%0], [%1], %2, [%3];"
                 :: "r"(dst), "l"(src), "r"(bytes), "r"(mbar) : "memory");
}

// ---- prep: padded chunk-blocked bf16 hi/lo weight images + xi/c1 ------------
__global__ void prep_kernel(const float* __restrict__ x, const int* __restrict__ ip,
                            const float* __restrict__ Wn2e, const float* __restrict__ bn2e,
                            const float* __restrict__ We2e) {
    int t = threadIdx.x;
    if (blockIdx.x == 480) {    // xi + c1
        __shared__ float xi[DIMF];
        int idx = ip[0];
        if (t < DIMF) { float v = x[idx * DIMF + t]; xi[t] = v; g_xi[t] = v; }
        __syncthreads();
        int w = t >> 5, lane = t & 31;
        for (int it = 0; it < 32; ++it) {
            int j = w * 32 + it;
            const float* wr = Wn2e + j * 256 + DIMF;
            float acc = 0.0f;
            #pragma unroll
            for (int i = 0; i < 4; ++i) acc += wr[lane + 32 * i] * xi[lane + 32 * i];
            #pragma unroll
            for (int o = 16; o >= 1; o >>= 1) acc += __shfl_down_sync(0xffffffffu, acc, o);
            if (lane == 0) g_c1[j] = acc + bn2e[j];
        }
        return;
    }
    // 122,880 bf16x2 slots: [gc 0..11][row 0..511][kpair 0..19]
    int gid = blockIdx.x * 256 + t;
    int gc = gid / 10240;
    int local = gid - gc * 10240;
    int row = local / 20;
    int kpair = local - row * 20;
    bool isWa = gc < 4;
    int chunk = isWa ? gc : gc - 4;
    __nv_bfloat16* dst = (isWa ? gWaP : gWeP) + ((size_t)(chunk * 512 + row)) * BSTR + kpair * 2;
    if (kpair >= 16) { *(unsigned*)dst = 0u; return; }
    int n = (row < 256) ? row : row - 256;
    int k = chunk * 32 + kpair * 2;
    const float* W = isWa ? Wn2e : We2e;     // both row-stride 256
    float2 p = make_float2(W[n * 256 + k], W[n * 256 + k + 1]);
    unsigned hi, lo;
    split2(p, hi, lo);
    *(unsigned*)dst = (row < 256) ? hi : lo;
}

// ---- main: HMMA bf16 split-3, bulk-DMA weight stream, fused tail ------------
__global__ void __launch_bounds__(512, 1)
main_kernel(const float* __restrict__ x, const float* __restrict__ adj,
            const float* __restrict__ be2e,
            const float* __restrict__ We2n, const float* __restrict__ be2n,
            const float* __restrict__ Wout, const float* __restrict__ bout,
            float* __restrict__ out, int N) {
    extern __shared__ __align__(16) __nv_bfloat16 dsm[];
    __nv_bfloat16* h1 = dsm;                         // [2][128][H1S]; also xs
    __nv_bfloat16* Bs = dsm + 2 * 128 * H1S;         // [2][512][BSTR]
    __shared__ float c1s[HIDF], b2s[HIDF], adjs[TM];
    __shared__ __align__(8) unsigned long long mbars[2];
    __shared__ unsigned s_islast;

    const int tid = threadIdx.x;
    const int w = tid >> 5, lane = tid & 31;
    const int g = lane >> 2, t = lane & 3;
    const int wn = w >> 1, wm = w & 1;
    const int nb = wn * 32;
    const int mbase = wm * 64;
    const int rbase = blockIdx.x * TM;

    if (tid < HIDF) { c1s[tid] = g_c1[tid]; b2s[tid] = be2e[tid]; }
    else if (tid < HIDF + TM) {
        int lt = tid - HIDF;
        int r = rbase + lt;
        adjs[lt] = (r < N) ? adj[r] : 0.0f;
    }

    const unsigned bs_u32 = smem_u32(Bs);
    const unsigned h1_u32 = smem_u32(h1);
    const unsigned mb = smem_u32(mbars);

    const int rr = lane & 7, q = lane >> 3;
    const unsigned arow_off = (unsigned)(((q & 1) << 3) + rr) * (H1S * 2);
    const unsigned akoff = (unsigned)((q >> 1) << 3) * 2;
    const int bsel = lane >> 3, bln = lane & 7;
    const unsigned b_off = (unsigned)((((bsel >> 1) << 3) + bln) * BSTR + ((bsel & 1) << 3)) * 2;

    float acc[4][4][4];
    unsigned Bh0[4], Bh1[4], Bl0[4], Bl1[4];

    // ---- stage x: split -> xs planes (aliased with h1) ----
    {
        int r = tid >> 2;
        int cq = (tid & 3) << 5;
        int row = rbase + r;
        float f[32];
        if (row < N) {
            const float4* xr = (const float4*)(x + (size_t)row * DIMF + cq);
            #pragma unroll
            for (int qq = 0; qq < 8; ++qq) {
                float4 v = xr[qq];
                f[4*qq] = v.x; f[4*qq+1] = v.y; f[4*qq+2] = v.z; f[4*qq+3] = v.w;
            }
        } else {
            #pragma unroll
            for (int qq = 0; qq < 32; ++qq) f[qq] = 0.0f;
        }
        #pragma unroll
        for (int p = 0; p < 8; ++p) {
            unsigned ha, la, hb, lb;
            split2(make_float2(f[4*p],   f[4*p+1]), ha, la);
            split2(make_float2(f[4*p+2], f[4*p+3]), hb, lb);
            int col = cq + 4 * p;
            *(uint2*)(h1 + (size_t)r * H1S + col)         = make_uint2(ha, hb);
            *(uint2*)(h1 + (size_t)(128 + r) * H1S + col) = make_uint2(la, lb);
        }
    }
    if (tid == 0) { MBI(mb, 1); MBI(mb + 8, 1); }
    __syncthreads();   // xs staged, mbars init'd, c1s/adjs ready

    if (tid == 0) {
        MBTX(mb, CHUNKB);
        bulk_g2s(bs_u32, gWaP, CHUNKB, mb);
    }

    // helper: global chunk gc source pointer
    // gc<4 -> gWaP + gc*20480 ; else gWeP + (gc-4)*20480   (bf16 elems)

    // =========================== GEMM 1 (gc 0..3) ===========================
    #pragma unroll
    for (int a = 0; a < 4; ++a)
        #pragma unroll
        for (int b = 0; b < 4; ++b)
            #pragma unroll
            for (int i = 0; i < 4; ++i) acc[a][b][i] = 0.0f;

    for (int gc = 0; gc < 4; ++gc) {
        if (tid == 0) {   // prefetch gc+1 (buffer free: last used gc-1, synced)
            int nx = gc + 1;
            const __nv_bfloat16* src = (nx < 4) ? (gWaP + (size_t)nx * 20480)
                                                : (gWeP + (size_t)(nx - 4) * 20480);
            unsigned mbar = mb + (unsigned)((nx & 1) * 8);
            MBTX(mbar, CHUNKB);
            bulk_g2s(bs_u32 + (unsigned)((nx & 1) * CHUNKB), src, CHUNKB, mbar);
        }
        MBWAIT(mb + (unsigned)((gc & 1) * 8), (gc >> 1) & 1);
        const unsigned bufb = bs_u32 + (unsigned)((gc & 1) * CHUNKB);
        #pragma unroll
        for (int kk = 0; kk < 2; ++kk) {
            const int kg = gc * 32 + kk * 16;
            const unsigned bb = bufb + (unsigned)((nb * BSTR + kk * 16) * 2) + b_off;
            { unsigned r4[4]; LDM4(r4, bb);
              Bh0[0]=r4[0]; Bh1[0]=r4[1]; Bh0[1]=r4[2]; Bh1[1]=r4[3]; }
            { unsigned r4[4]; LDM4(r4, bb + 16 * BSTR * 2);
              Bh0[2]=r4[0]; Bh1[2]=r4[1]; Bh0[3]=r4[2]; Bh1[3]=r4[3]; }
            { unsigned r4[4]; LDM4(r4, bb + 256 * BSTR * 2);
              Bl0[0]=r4[0]; Bl1[0]=r4[1]; Bl0[1]=r4[2]; Bl1[1]=r4[3]; }
            { unsigned r4[4]; LDM4(r4, bb + (256 + 16) * BSTR * 2);
              Bl0[2]=r4[0]; Bl1[2]=r4[1]; Bl0[3]=r4[2]; Bl1[3]=r4[3]; }
            #pragma unroll
            for (int mt = 0; mt < 4; ++mt) {
                unsigned base = h1_u32 + (unsigned)(mbase + mt * 16) * (H1S * 2)
                                + arow_off + (unsigned)kg * 2 + akoff;
                unsigned ah[4], al[4];
                LDM4(ah, base);
                LDM4(al, base + 128 * H1S * 2);
                #pragma unroll
                for (int nt = 0; nt < 4; ++nt) MMA(acc[mt][nt], ah, Bh0[nt], Bh1[nt]);
                #pragma unroll
                for (int nt = 0; nt < 4; ++nt) MMA(acc[mt][nt], ah, Bl0[nt], Bl1[nt]);
                #pragma unroll
                for (int nt = 0; nt < 4; ++nt) MMA(acc[mt][nt], al, Bh0[nt], Bh1[nt]);
            }
        }
        __syncthreads();   // all done reading this buffer
    }
    // epilogue 1: relu(acc + c1) -> split -> h1
    #pragma unroll
    for (int mt = 0; mt < 4; ++mt) {
        int lr0 = mbase + mt * 16 + g;
        #pragma unroll
        for (int nt = 0; nt < 4; ++nt) {
            int col = nb + nt * 8 + 2 * t;
            float b0 = c1s[col], b1 = c1s[col + 1];
            float v0 = fmaxf(acc[mt][nt][0] + b0, 0.0f);
            float v1 = fmaxf(acc[mt][nt][1] + b1, 0.0f);
            float v2 = fmaxf(acc[mt][nt][2] + b0, 0.0f);
            float v3 = fmaxf(acc[mt][nt][3] + b1, 0.0f);
            unsigned hi, lo;
            split2(make_float2(v0, v1), hi, lo);
            *(unsigned*)(h1 + (size_t)lr0 * H1S + col) = hi;
            *(unsigned*)(h1 + (size_t)(128 + lr0) * H1S + col) = lo;
            split2(make_float2(v2, v3), hi, lo);
            *(unsigned*)(h1 + (size_t)(lr0 + 8) * H1S + col) = hi;
            *(unsigned*)(h1 + (size_t)(136 + lr0) * H1S + col) = lo;
        }
    }
    __syncthreads();   // h1 complete before GEMM2 reads it

    // =========================== GEMM 2 (gc 4..11) ===========================
    #pragma unroll
    for (int a = 0; a < 4; ++a)
        #pragma unroll
        for (int b = 0; b < 4; ++b)
            #pragma unroll
            for (int i = 0; i < 4; ++i) acc[a][b][i] = 0.0f;

    for (int gc = 4; gc < 12; ++gc) {
        if (tid == 0 && gc < 11) {
            int nx = gc + 1;
            const __nv_bfloat16* src = gWeP + (size_t)(nx - 4) * 20480;
            unsigned mbar = mb + (unsigned)((nx & 1) * 8);
            MBTX(mbar, CHUNKB);
            bulk_g2s(bs_u32 + (unsigned)((nx & 1) * CHUNKB), src, CHUNKB, mbar);
        }
        MBWAIT(mb + (unsigned)((gc & 1) * 8), (gc >> 1) & 1);
        const unsigned bufb = bs_u32 + (unsigned)((gc & 1) * CHUNKB);
        #pragma unroll
        for (int kk = 0; kk < 2; ++kk) {
            const int kg = (gc - 4) * 32 + kk * 16;
            const unsigned bb = bufb + (unsigned)((nb * BSTR + kk * 16) * 2) + b_off;
            { unsigned r4[4]; LDM4(r4, bb);
              Bh0[0]=r4[0]; Bh1[0]=r4[1]; Bh0[1]=r4[2]; Bh1[1]=r4[3]; }
            { unsigned r4[4]; LDM4(r4, bb + 16 * BSTR * 2);
              Bh0[2]=r4[0]; Bh1[2]=r4[1]; Bh0[3]=r4[2]; Bh1[3]=r4[3]; }
            { unsigned r4[4]; LDM4(r4, bb + 256 * BSTR * 2);
              Bl0[0]=r4[0]; Bl1[0]=r4[1]; Bl0[1]=r4[2]; Bl1[1]=r4[3]; }
            { unsigned r4[4]; LDM4(r4, bb + (256 + 16) * BSTR * 2);
              Bl0[2]=r4[0]; Bl1[2]=r4[1]; Bl0[3]=r4[2]; Bl1[3]=r4[3]; }
            #pragma unroll
            for (int mt = 0; mt < 4; ++mt) {
                unsigned base = h1_u32 + (unsigned)(mbase + mt * 16) * (H1S * 2)
                                + arow_off + (unsigned)kg * 2 + akoff;
                unsigned ah[4], al[4];
                LDM4(ah, base);
                LDM4(al, base + 128 * H1S * 2);
                #pragma unroll
                for (int nt = 0; nt < 4; ++nt) MMA(acc[mt][nt], ah, Bh0[nt], Bh1[nt]);
                #pragma unroll
                for (int nt = 0; nt < 4; ++nt) MMA(acc[mt][nt], ah, Bl0[nt], Bl1[nt]);
                #pragma unroll
                for (int nt = 0; nt < 4; ++nt) MMA(acc[mt][nt], al, Bh0[nt], Bh1[nt]);
            }
        }
        __syncthreads();
    }
    // epilogue 2: relu(acc + b2) * adj, column sums
    float colsum[4][2];
    #pragma unroll
    for (int nt = 0; nt < 4; ++nt) { colsum[nt][0] = 0.0f; colsum[nt][1] = 0.0f; }
    #pragma unroll
    for (int mt = 0; mt < 4; ++mt) {
        int lr0 = mbase + mt * 16 + g;
        float a0 = adjs[lr0], a8 = adjs[lr0 + 8];
        #pragma unroll
        for (int nt = 0; nt < 4; ++nt) {
            int col = nb + nt * 8 + 2 * t;
            float b0 = b2s[col], b1 = b2s[col + 1];
            colsum[nt][0] += fmaxf(acc[mt][nt][0] + b0, 0.0f) * a0
                           + fmaxf(acc[mt][nt][2] + b0, 0.0f) * a8;
            colsum[nt][1] += fmaxf(acc[mt][nt][1] + b1, 0.0f) * a0
                           + fmaxf(acc[mt][nt][3] + b1, 0.0f) * a8;
        }
    }
    #pragma unroll
    for (int nt = 0; nt < 4; ++nt) {
        #pragma unroll
        for (int j = 0; j < 2; ++j) {
            float v = colsum[nt][j];
            v += __shfl_down_sync(0xffffffffu, v, 16);
            v += __shfl_down_sync(0xffffffffu, v, 8);
            v += __shfl_down_sync(0xffffffffu, v, 4);
            if (lane < 4)
                g_partials[(size_t)(blockIdx.x * 2 + wm) * HIDF + nb + nt * 8 + 2 * lane + j] = v;
        }
    }

    // ---- fused tail: last CTA reduces partials + small MLPs ----
    __syncthreads();
    if (tid == 0) {
        __threadfence();
        unsigned old = atomicAdd(&g_ctr, 1u);
        s_islast = (old == gridDim.x - 1) ? 1u : 0u;
    }
    __syncthreads();
    if (!s_islast) return;
    __threadfence();

    __shared__ float ss[HIDF];
    __shared__ float sv[DIMF + HIDF];
    const int R = gridDim.x * 2;
    {
        int col = tid & 255, half = tid >> 8;
        float a = 0.0f;
        for (int r = half; r < R; r += 2) a += g_partials[(size_t)r * HIDF + col];
        if (half == 0) ss[col] = a;
        __syncthreads();
        if (half == 1) ss[col] += a;
    }
    if (tid < DIMF) sv[tid] = g_xi[tid];
    __syncthreads();
    for (int it = 0; it < 16; ++it) {
        int row = w * 16 + it;
        const float* wr = We2n + row * HIDF;
        float a = 0.0f;
        #pragma unroll
        for (int i = 0; i < 8; ++i) a += wr[lane + 32 * i] * ss[lane + 32 * i];
        #pragma unroll
        for (int o = 16; o >= 1; o >>= 1) a += __shfl_down_sync(0xffffffffu, a, o);
        if (lane == 0) sv[DIMF + row] = a + be2n[row];
    }
    __syncthreads();
    for (int it = 0; it < 8; ++it) {
        int row = w * 8 + it;
        const float* wr = Wout + row * (DIMF + HIDF);
        float a = 0.0f;
        #pragma unroll
        for (int i = 0; i < 12; ++i) a += wr[lane + 32 * i] * sv[lane + 32 * i];
        #pragma unroll
        for (int o = 16; o >= 1; o >>= 1) a += __shfl_down_sync(0xffffffffu, a, o);
        if (lane == 0) out[row] = sv[row] + a + bout[row];
    }
    if (tid == 0) g_ctr = 0;
}

extern "C" void kernel_launch(void* const* d_in, const int* in_sizes, int n_in,
                              void* d_out, int out_size) {
    const float* x    = (const float*)d_in[0];
    const float* adj  = (const float*)d_in[1];
    const int*   ip   = (const int*)  d_in[2];
    const float* Wn2e = (const float*)d_in[3];
    const float* bn2e = (const float*)d_in[4];
    const float* We2e = (const float*)d_in[5];
    const float* be2e = (const float*)d_in[6];
    const float* We2n = (const float*)d_in[7];
    const float* be2n = (const float*)d_in[8];
    const float* Wout = (const float*)d_in[9];
    const float* bout = (const float*)d_in[10];
    float* out = (float*)d_out;

    const int N = in_sizes[1];
    const int nblk = (N + TM - 1) / TM;
    const int dyn = (2 * 128 * H1S + 2 * 512 * BSTR) * 2;   // 217,088 bytes
    cudaFuncSetAttribute(main_kernel, cudaFuncAttributeMaxDynamicSharedMemorySize, dyn);

    prep_kernel<<<481, 256>>>(x, ip, Wn2e, bn2e, We2e);
    main_kernel<<<nblk, 512, dyn>>>(x, adj, be2e, We2n, be2n, Wout, bout, out, N);
}